// round 13
// baseline (speedup 1.0000x reference)
#include <cuda_runtime.h>
#include <cuda_bf16.h>
#include <math.h>

#define MAXA 54
#define NN   (1024*MAXA)      /* 55296 nodes  */
#define DEG  16
#define NE   (NN*DEG)         /* 884736 edges */
#define MMM  16
#define TILE_E 128
#define NTILES (NE/TILE_E)    /* 6912 */
#define NPT  (TILE_E/DEG)     /* 8 */
#define STRIDE 68

typedef unsigned long long u64;

__device__ float g_h1 [(size_t)NN*64];
__device__ float g_P  [(size_t)NN*64];
__device__ float g_Q  [(size_t)NN*64];
__device__ float g_agg[(size_t)NN*64];

__device__ __forceinline__ u64 pk(float lo, float hi){u64 r;asm("mov.b64 %0,{%1,%2};":"=l"(r):"f"(lo),"f"(hi));return r;}
__device__ __forceinline__ void upk(u64 v,float&lo,float&hi){asm("mov.b64 {%0,%1},%2;":"=f"(lo),"=f"(hi):"l"(v));}
__device__ __forceinline__ void fma2(u64&d,u64 a,u64 b){asm("fma.rn.f32x2 %0,%1,%2,%0;":"+l"(d):"l"(a),"l"(b));}
__device__ __forceinline__ float silu(float x){return __fdividef(x, 1.f + __expf(-x));}
__device__ __forceinline__ void red4(float*p,float a,float b,float c,float d){
    asm volatile("red.global.add.v4.f32 [%0],{%1,%2,%3,%4};"::"l"(p),"f"(a),"f"(b),"f"(c),"f"(d):"memory");}

/* ---- 4-rows-per-thread GEMM (prep/nodes kernels, 256 thr) ---- */
template<int K>
__device__ __forceinline__ void gemm4(const float* __restrict__ X,const float* __restrict__ W,
                                      int ty,int c0,u64 acc[4][4]){
#pragma unroll 2
    for(int k4=0;k4<K/4;++k4){
        float4 xv[4];
#pragma unroll
        for(int i=0;i<4;++i) xv[i]=*(const float4*)(X+(ty*4+i)*STRIDE+k4*4);
#pragma unroll
        for(int kk=0;kk<4;++kk){
            const float* Wk=W+(k4*4+kk)*64;
            float4 wa=*(const float4*)(Wk+c0), wb=*(const float4*)(Wk+c0+32);
            u64 w0=pk(wa.x,wa.y),w1=pk(wa.z,wa.w),w2=pk(wb.x,wb.y),w3=pk(wb.z,wb.w);
#pragma unroll
            for(int i=0;i<4;++i){
                float x=(kk==0)?xv[i].x:(kk==1)?xv[i].y:(kk==2)?xv[i].z:xv[i].w;
                u64 xp=pk(x,x);
                fma2(acc[i][0],xp,w0);fma2(acc[i][1],xp,w1);
                fma2(acc[i][2],xp,w2);fma2(acc[i][3],xp,w3);
            }
        }
    }
}

/* ---- 2-rows-per-thread GEMM (edge kernel, 512 thr) ---- */
template<int K>
__device__ __forceinline__ void gemm2(const float* __restrict__ X,const float* __restrict__ W,
                                      int ty,int c0,u64 acc[2][4]){
#pragma unroll 2
    for(int k4=0;k4<K/4;++k4){
        float4 xv[2];
#pragma unroll
        for(int i=0;i<2;++i) xv[i]=*(const float4*)(X+(ty*2+i)*STRIDE+k4*4);
#pragma unroll
        for(int kk=0;kk<4;++kk){
            const float* Wk=W+(k4*4+kk)*64;
            float4 wa=*(const float4*)(Wk+c0), wb=*(const float4*)(Wk+c0+32);
            u64 w0=pk(wa.x,wa.y),w1=pk(wa.z,wa.w),w2=pk(wb.x,wb.y),w3=pk(wb.z,wb.w);
#pragma unroll
            for(int i=0;i<2;++i){
                float x=(kk==0)?xv[i].x:(kk==1)?xv[i].y:(kk==2)?xv[i].z:xv[i].w;
                u64 xp=pk(x,x);
                fma2(acc[i][0],xp,w0);fma2(acc[i][1],xp,w1);
                fma2(acc[i][2],xp,w2);fma2(acc[i][3],xp,w3);
            }
        }
    }
}

/* =================== Kernel A: prep =================== */
#define A_W1A 0
#define A_W1B 4096
#define A_SH1 8192
#define A_SMEMF (8192+128*STRIDE)
__global__ void __launch_bounds__(256,1)
kernel_prep(const float* __restrict__ h,const float* __restrict__ node_embed,
            const float* __restrict__ mes_w1,const int* __restrict__ node_holder,
            const int* __restrict__ jt_idx){
    extern __shared__ float s[];
    const int tid=threadIdx.x, nb=blockIdx.x*128;
    for(int i=tid;i<4096;i+=256){s[A_W1A+i]=mes_w1[i];s[A_W1B+i]=mes_w1[4096+i];}
    for(int i=tid;i<128*64;i+=256){
        int l=i>>6,o=i&63,node=nb+l,cand=node/MAXA;
        int jn=node_holder[node],j=jt_idx[cand],jn1=jn>0?jn-1:0;
        float v=h[(size_t)node*64+o]+node_embed[((size_t)j*MMM+jn1)*64+o];
        s[A_SH1+l*STRIDE+o]=v; g_h1[(size_t)node*64+o]=v; g_agg[(size_t)node*64+o]=0.f;
    }
    __syncthreads();
    const int tx=tid&7, ty=tid>>3, c0=tx*4;
    u64 acc[4][4];
#pragma unroll
    for(int i=0;i<4;++i)
#pragma unroll
        for(int p=0;p<4;++p) acc[i][p]=0ull;
    gemm4<64>(s+A_SH1,s+A_W1A,ty,c0,acc);
#pragma unroll
    for(int i=0;i<4;++i){
        size_t b=(size_t)(nb+ty*4+i)*64; float v[8];
#pragma unroll
        for(int p=0;p<4;++p) upk(acc[i][p],v[2*p],v[2*p+1]);
        *(float4*)(g_P+b+c0)=make_float4(v[0],v[1],v[2],v[3]);
        *(float4*)(g_P+b+c0+32)=make_float4(v[4],v[5],v[6],v[7]);
    }
#pragma unroll
    for(int i=0;i<4;++i)
#pragma unroll
        for(int p=0;p<4;++p) acc[i][p]=0ull;
    gemm4<64>(s+A_SH1,s+A_W1B,ty,c0,acc);
#pragma unroll
    for(int i=0;i<4;++i){
        size_t b=(size_t)(nb+ty*4+i)*64; float v[8];
#pragma unroll
        for(int p=0;p<4;++p) upk(acc[i][p],v[2*p],v[2*p+1]);
        *(float4*)(g_Q+b+c0)=make_float4(v[0],v[1],v[2],v[3]);
        *(float4*)(g_Q+b+c0+32)=make_float4(v[4],v[5],v[6],v[7]);
    }
}

/* =================== Kernel B: edges (512 thr) =================== */
#define OFF_W1E  0
#define OFF_W2   4096
#define OFF_CW1  8192
#define OFF_EW1  12288
#define OFF_EW2  20544
#define OFF_W1R  24640
#define OFF_B1   24704
#define OFF_B2   24768
#define OFF_CB1  24832
#define OFF_CW2  24896
#define OFF_EB1  24960
#define OFF_EB2  25024
#define OFF_BUFE 25088
#define OFF_BUFT 33792
#define OFF_BUFF 42496
#define OFF_SCOL 51200
#define OFF_SMB  51328
#define OFF_SEM  51456
#define OFF_SRAD 51584
#define OFF_SCD  51712
#define OFF_SGT  52096
#define OFF_STR  52224
#define B_SMEMF  52608
#define TB 512

__global__ void __launch_bounds__(TB,1)
kernel_edges(const float* __restrict__ coord,const float* __restrict__ edge_attr,
             const float* __restrict__ jt_mess,const float* __restrict__ node_mask,
             const float* __restrict__ edge_mask,
             const float* __restrict__ mes_w1,const float* __restrict__ mes_b1,
             const float* __restrict__ mes_w2,const float* __restrict__ mes_b2,
             const float* __restrict__ edge_w1,const float* __restrict__ edge_b1,
             const float* __restrict__ edge_w2,const float* __restrict__ edge_b2,
             const float* __restrict__ coord_w1,const float* __restrict__ coord_b1,
             const float* __restrict__ coord_w2,
             const int* __restrict__ colidx,const int* __restrict__ mess_holder,
             const int* __restrict__ jt_idx,
             float* __restrict__ outC,float* __restrict__ outE){
    extern __shared__ float s[];
    int* scol=(int*)(s+OFF_SCOL); int* smb=(int*)(s+OFF_SMB);
    const int tid=threadIdx.x;
    const int tx=tid&7, ty=tid>>3;   /* ty 0..63, rows ty*2, ty*2+1 */
    const int c0=tx*4;

    for(int i=tid;i<4096;i+=TB){
        s[OFF_W1E+i]=mes_w1[129*64+i];
        s[OFF_W2 +i]=mes_w2[i];
        s[OFF_CW1+i]=coord_w1[i];
        s[OFF_EW2+i]=edge_w2[i];
    }
    for(int i=tid;i<8256;i+=TB) s[OFF_EW1+i]=edge_w1[i];
    if(tid<64){
        s[OFF_W1R+tid]=mes_w1[128*64+tid];
        s[OFF_B1 +tid]=mes_b1[tid];
        s[OFF_B2 +tid]=mes_b2[tid];
        s[OFF_CB1+tid]=coord_b1[tid];
        s[OFF_CW2+tid]=coord_w2[tid];
        s[OFF_EB1+tid]=edge_b1[tid];
        s[OFF_EB2+tid]=edge_b2[tid];
    }
    __syncthreads();

    for(int tile=blockIdx.x;tile<NTILES;tile+=gridDim.x){
        const int e0=tile*TILE_E;
        const int r0=ty*2, eg0=e0+r0;
        const int nr=eg0>>4;           /* same node for both rows (r0 even) */

        /* ---- early prefetch: cols + P + Q (in flight through GEMM1) ---- */
        const int col0=colidx[eg0], col1=colidx[eg0+1];
        float4 pA =*(const float4*)(g_P+(size_t)nr  *64+c0);
        float4 pB =*(const float4*)(g_P+(size_t)nr  *64+c0+32);
        float4 q0A=*(const float4*)(g_Q+(size_t)col0*64+c0);
        float4 q0B=*(const float4*)(g_Q+(size_t)col0*64+c0+32);
        float4 q1A=*(const float4*)(g_Q+(size_t)col1*64+c0);
        float4 q1B=*(const float4*)(g_Q+(size_t)col1*64+c0+32);

        /* ---- per-edge metadata ---- */
        if(tid<128){
            int ee=e0+tid, c=colidx[ee]; scol[tid]=c;
            int rr=ee>>4, cand=rr/MAXA, am=rr-cand*MAXA, ac=c-cand*MAXA;
            const int* jp=mess_holder+((((size_t)cand*MAXA+am)*MAXA+ac)<<1);
            int jr=jp[0],jc=jp[1],mb=-1;
            if(jr!=0&&jc!=0) mb=((jt_idx[cand]*MMM+(jr-1))*MMM+(jc-1))*64;
            smb[tid]=mb;
            s[OFF_SEM+tid]=edge_mask[ee];
            float dx=coord[rr*3+0]-coord[c*3+0];
            float dy=coord[rr*3+1]-coord[c*3+1];
            float dz=coord[rr*3+2]-coord[c*3+2];
            float rad=dx*dx+dy*dy+dz*dz; s[OFF_SRAD+tid]=rad;
            float inv=1.f/(sqrtf(rad+1e-8f)+1.f);
            s[OFF_SCD+tid*3+0]=dx*inv; s[OFF_SCD+tid*3+1]=dy*inv; s[OFF_SCD+tid*3+2]=dz*inv;
        }
        __syncthreads();

        /* ---- stage bufE = edge_attr + mess ---- */
        for(int idx=tid;idx<128*16;idx+=TB){
            int e=idx>>4,o4=(idx&15)<<2;
            int eg=e0+e, mb=smb[e];
            float4 v=*(const float4*)(edge_attr+(size_t)eg*64+o4);
            if(mb>=0){ float4 m=*(const float4*)(jt_mess+(size_t)mb+o4);
                v.x+=m.x;v.y+=m.y;v.z+=m.z;v.w+=m.w; }
            *(float4*)(s+OFF_BUFE+e*STRIDE+o4)=v;
        }
        __syncthreads();

        u64 acc[2][4];

        /* ---- GEMM1: bufE @ W1E ; + P + Q + rad*w1r + b1 ; silu -> bufT ---- */
#pragma unroll
        for(int i=0;i<2;++i)
#pragma unroll
            for(int p=0;p<4;++p) acc[i][p]=0ull;
        gemm2<64>(s+OFF_BUFE,s+OFF_W1E,ty,c0,acc);
        {
            float bA0=s[OFF_B1+c0],bA1=s[OFF_B1+c0+1],bA2=s[OFF_B1+c0+2],bA3=s[OFF_B1+c0+3];
            float bB0=s[OFF_B1+c0+32],bB1=s[OFF_B1+c0+33],bB2=s[OFF_B1+c0+34],bB3=s[OFF_B1+c0+35];
            float wA0=s[OFF_W1R+c0],wA1=s[OFF_W1R+c0+1],wA2=s[OFF_W1R+c0+2],wA3=s[OFF_W1R+c0+3];
            float wB0=s[OFF_W1R+c0+32],wB1=s[OFF_W1R+c0+33],wB2=s[OFF_W1R+c0+34],wB3=s[OFF_W1R+c0+35];
#pragma unroll
            for(int i=0;i<2;++i){
                int e=r0+i; float rad=s[OFF_SRAD+e];
                float4 qA = i? q1A:q0A, qB = i? q1B:q0B;
                float* d=s+OFF_BUFT+e*STRIDE;
                float a,b;
                upk(acc[i][0],a,b);
                d[c0+0]=silu(a+bA0+rad*wA0+pA.x+qA.x);
                d[c0+1]=silu(b+bA1+rad*wA1+pA.y+qA.y);
                upk(acc[i][1],a,b);
                d[c0+2]=silu(a+bA2+rad*wA2+pA.z+qA.z);
                d[c0+3]=silu(b+bA3+rad*wA3+pA.w+qA.w);
                upk(acc[i][2],a,b);
                d[c0+32]=silu(a+bB0+rad*wB0+pB.x+qB.x);
                d[c0+33]=silu(b+bB1+rad*wB1+pB.y+qB.y);
                upk(acc[i][3],a,b);
                d[c0+34]=silu(a+bB2+rad*wB2+pB.z+qB.z);
                d[c0+35]=silu(b+bB3+rad*wB3+pB.w+qB.w);
            }
        }
        __syncthreads();

        /* ---- GEMM2: bufT @ W2 ; silu(+b2)*em -> bufF + agg red ---- */
#pragma unroll
        for(int i=0;i<2;++i)
#pragma unroll
            for(int p=0;p<4;++p) acc[i][p]=0ull;
        gemm2<64>(s+OFF_BUFT,s+OFF_W2,ty,c0,acc);
#pragma unroll
        for(int i=0;i<2;++i){
            int e=r0+i; float em=s[OFF_SEM+e];
            int c = i? col1:col0;
            float* d=s+OFF_BUFF+e*STRIDE;
            float* ga=g_agg+(size_t)c*64;
            float a,b,v0,v1,v2,v3;
            upk(acc[i][0],a,b); v0=silu(a+s[OFF_B2+c0  ])*em; v1=silu(b+s[OFF_B2+c0+1])*em;
            upk(acc[i][1],a,b); v2=silu(a+s[OFF_B2+c0+2])*em; v3=silu(b+s[OFF_B2+c0+3])*em;
            d[c0+0]=v0;d[c0+1]=v1;d[c0+2]=v2;d[c0+3]=v3;
            red4(ga+c0,v0,v1,v2,v3);
            upk(acc[i][2],a,b); v0=silu(a+s[OFF_B2+c0+32])*em; v1=silu(b+s[OFF_B2+c0+33])*em;
            upk(acc[i][3],a,b); v2=silu(a+s[OFF_B2+c0+34])*em; v3=silu(b+s[OFF_B2+c0+35])*em;
            d[c0+32]=v0;d[c0+33]=v1;d[c0+34]=v2;d[c0+35]=v3;
            red4(ga+c0+32,v0,v1,v2,v3);
        }
        __syncthreads();

        /* ---- GEMM3: coord gate ---- */
#pragma unroll
        for(int i=0;i<2;++i)
#pragma unroll
            for(int p=0;p<4;++p) acc[i][p]=0ull;
        gemm2<64>(s+OFF_BUFF,s+OFF_CW1,ty,c0,acc);
        {
            float cA0=s[OFF_CW2+c0],cA1=s[OFF_CW2+c0+1],cA2=s[OFF_CW2+c0+2],cA3=s[OFF_CW2+c0+3];
            float cB0=s[OFF_CW2+c0+32],cB1=s[OFF_CW2+c0+33],cB2=s[OFF_CW2+c0+34],cB3=s[OFF_CW2+c0+35];
#pragma unroll
            for(int i=0;i<2;++i){
                float pd=0.f,a,b;
                upk(acc[i][0],a,b); pd+=silu(a+s[OFF_CB1+c0  ])*cA0+silu(b+s[OFF_CB1+c0+1])*cA1;
                upk(acc[i][1],a,b); pd+=silu(a+s[OFF_CB1+c0+2])*cA2+silu(b+s[OFF_CB1+c0+3])*cA3;
                upk(acc[i][2],a,b); pd+=silu(a+s[OFF_CB1+c0+32])*cB0+silu(b+s[OFF_CB1+c0+33])*cB1;
                upk(acc[i][3],a,b); pd+=silu(a+s[OFF_CB1+c0+34])*cB2+silu(b+s[OFF_CB1+c0+35])*cB3;
                pd+=__shfl_xor_sync(0xffffffffu,pd,1);
                pd+=__shfl_xor_sync(0xffffffffu,pd,2);
                pd+=__shfl_xor_sync(0xffffffffu,pd,4);
                if(tx==0) s[OFF_SGT+r0+i]=pd;
            }
        }
        __syncthreads();

        if(tid<128){
            float g=s[OFF_SGT+tid]*s[OFF_SEM+tid];
            s[OFF_STR+tid*3+0]=s[OFF_SCD+tid*3+0]*g;
            s[OFF_STR+tid*3+1]=s[OFF_SCD+tid*3+1]*g;
            s[OFF_STR+tid*3+2]=s[OFF_SCD+tid*3+2]*g;
        }
        __syncthreads();
        if(tid<NPT*3){
            int n=tid/3,c=tid-n*3; float sum=0.f;
#pragma unroll
            for(int k=0;k<DEG;++k) sum+=s[OFF_STR+(n*DEG+k)*3+c];
            int gn=tile*NPT+n;
            outC[gn*3+c]=(coord[gn*3+c]+sum)*node_mask[gn];
        }

        /* ---- GEMM4: bufF @ EW1a + bufE @ EW1b ; silu(+eb1+rad*ew1r) -> bufT */
#pragma unroll
        for(int i=0;i<2;++i)
#pragma unroll
            for(int p=0;p<4;++p) acc[i][p]=0ull;
        gemm2<64>(s+OFF_BUFF,s+OFF_EW1,       ty,c0,acc);
        gemm2<64>(s+OFF_BUFE,s+OFF_EW1+65*64, ty,c0,acc);
        {
            float bA0=s[OFF_EB1+c0],bA1=s[OFF_EB1+c0+1],bA2=s[OFF_EB1+c0+2],bA3=s[OFF_EB1+c0+3];
            float bB0=s[OFF_EB1+c0+32],bB1=s[OFF_EB1+c0+33],bB2=s[OFF_EB1+c0+34],bB3=s[OFF_EB1+c0+35];
            float wA0=s[OFF_EW1+64*64+c0],wA1=s[OFF_EW1+64*64+c0+1],wA2=s[OFF_EW1+64*64+c0+2],wA3=s[OFF_EW1+64*64+c0+3];
            float wB0=s[OFF_EW1+64*64+c0+32],wB1=s[OFF_EW1+64*64+c0+33],wB2=s[OFF_EW1+64*64+c0+34],wB3=s[OFF_EW1+64*64+c0+35];
#pragma unroll
            for(int i=0;i<2;++i){
                int e=r0+i; float rad=s[OFF_SRAD+e];
                float* d=s+OFF_BUFT+e*STRIDE;
                float a,b;
                upk(acc[i][0],a,b); d[c0+0]=silu(a+bA0+rad*wA0); d[c0+1]=silu(b+bA1+rad*wA1);
                upk(acc[i][1],a,b); d[c0+2]=silu(a+bA2+rad*wA2); d[c0+3]=silu(b+bA3+rad*wA3);
                upk(acc[i][2],a,b); d[c0+32]=silu(a+bB0+rad*wB0); d[c0+33]=silu(b+bB1+rad*wB1);
                upk(acc[i][3],a,b); d[c0+34]=silu(a+bB2+rad*wB2); d[c0+35]=silu(b+bB3+rad*wB3);
            }
        }
        __syncthreads();

        /* ---- GEMM5: bufT @ EW2 ; (+eb2)*em -> outE ---- */
#pragma unroll
        for(int i=0;i<2;++i)
#pragma unroll
            for(int p=0;p<4;++p) acc[i][p]=0ull;
        gemm2<64>(s+OFF_BUFT,s+OFF_EW2,ty,c0,acc);
#pragma unroll
        for(int i=0;i<2;++i){
            int e=r0+i; float em=s[OFF_SEM+e];
            size_t eg=(size_t)(e0+e);
            float a,b,v0,v1,v2,v3;
            upk(acc[i][0],a,b); v0=(a+s[OFF_EB2+c0  ])*em; v1=(b+s[OFF_EB2+c0+1])*em;
            upk(acc[i][1],a,b); v2=(a+s[OFF_EB2+c0+2])*em; v3=(b+s[OFF_EB2+c0+3])*em;
            *(float4*)(outE+eg*64+c0)=make_float4(v0,v1,v2,v3);
            upk(acc[i][2],a,b); v0=(a+s[OFF_EB2+c0+32])*em; v1=(b+s[OFF_EB2+c0+33])*em;
            upk(acc[i][3],a,b); v2=(a+s[OFF_EB2+c0+34])*em; v3=(b+s[OFF_EB2+c0+35])*em;
            *(float4*)(outE+eg*64+c0+32)=make_float4(v0,v1,v2,v3);
        }
        __syncthreads();
    }
}

/* =================== Kernel C: node MLP =================== */
#define C_NW1 0
#define C_NW2 8192
#define C_NB1 12288
#define C_NB2 12352
#define C_BA  12416
#define C_BB  (12416+128*STRIDE)
#define C_BT  (12416+2*128*STRIDE)
#define C_SMEMF (12416+3*128*STRIDE)
__global__ void __launch_bounds__(256,1)
kernel_nodes(const float* __restrict__ node_w1,const float* __restrict__ node_b1,
             const float* __restrict__ node_w2,const float* __restrict__ node_b2,
             const float* __restrict__ node_mask,float* __restrict__ outH){
    extern __shared__ float s[];
    const int tid=threadIdx.x, nb=blockIdx.x*128;
    const int tx=tid&7, ty=tid>>3, c0=tx*4;
    for(int i=tid;i<8192;i+=256) s[C_NW1+i]=node_w1[i];
    for(int i=tid;i<4096;i+=256) s[C_NW2+i]=node_w2[i];
    if(tid<64){s[C_NB1+tid]=node_b1[tid];s[C_NB2+tid]=node_b2[tid];}
    for(int i=tid;i<128*16;i+=256){
        int l=i>>4,o4=(i&15)<<2; size_t b=(size_t)(nb+l)*64+o4;
        *(float4*)(s+C_BA+l*STRIDE+o4)=*(const float4*)(g_h1+b);
        *(float4*)(s+C_BB+l*STRIDE+o4)=*(const float4*)(g_agg+b);
    }
    __syncthreads();
    u64 acc[4][4];
#pragma unroll
    for(int i=0;i<4;++i){
        acc[i][0]=pk(s[C_NB1+c0],s[C_NB1+c0+1]);acc[i][1]=pk(s[C_NB1+c0+2],s[C_NB1+c0+3]);
        acc[i][2]=pk(s[C_NB1+c0+32],s[C_NB1+c0+33]);acc[i][3]=pk(s[C_NB1+c0+34],s[C_NB1+c0+35]);
    }
    gemm4<64>(s+C_BA,s+C_NW1,ty,c0,acc);
    gemm4<64>(s+C_BB,s+C_NW1+64*64,ty,c0,acc);
#pragma unroll
    for(int i=0;i<4;++i){
        float* d=s+C_BT+(ty*4+i)*STRIDE; float a,b;
        upk(acc[i][0],a,b);d[c0+0]=silu(a);d[c0+1]=silu(b);
        upk(acc[i][1],a,b);d[c0+2]=silu(a);d[c0+3]=silu(b);
        upk(acc[i][2],a,b);d[c0+32]=silu(a);d[c0+33]=silu(b);
        upk(acc[i][3],a,b);d[c0+34]=silu(a);d[c0+35]=silu(b);
    }
    __syncthreads();
#pragma unroll
    for(int i=0;i<4;++i){
        acc[i][0]=pk(s[C_NB2+c0],s[C_NB2+c0+1]);acc[i][1]=pk(s[C_NB2+c0+2],s[C_NB2+c0+3]);
        acc[i][2]=pk(s[C_NB2+c0+32],s[C_NB2+c0+33]);acc[i][3]=pk(s[C_NB2+c0+34],s[C_NB2+c0+35]);
    }
    gemm4<64>(s+C_BT,s+C_NW2,ty,c0,acc);
#pragma unroll
    for(int i=0;i<4;++i){
        int l=ty*4+i,node=nb+l; float nm=node_mask[node];
        const float* h1p=s+C_BA+l*STRIDE; float a,b,v0,v1,v2,v3;
        size_t base=(size_t)node*64;
        upk(acc[i][0],a,b);v0=(h1p[c0+0]+a)*nm;v1=(h1p[c0+1]+b)*nm;
        upk(acc[i][1],a,b);v2=(h1p[c0+2]+a)*nm;v3=(h1p[c0+3]+b)*nm;
        *(float4*)(outH+base+c0)=make_float4(v0,v1,v2,v3);
        upk(acc[i][2],a,b);v0=(h1p[c0+32]+a)*nm;v1=(h1p[c0+33]+b)*nm;
        upk(acc[i][3],a,b);v2=(h1p[c0+34]+a)*nm;v3=(h1p[c0+35]+b)*nm;
        *(float4*)(outH+base+c0+32)=make_float4(v0,v1,v2,v3);
    }
}

/* =================== launcher =================== */
extern "C" void kernel_launch(void* const* d_in, const int* in_sizes, int n_in,
                              void* d_out, int out_size)
{
    const float* h          =(const float*)d_in[0];
    const float* coord      =(const float*)d_in[1];
    const float* edge_attr  =(const float*)d_in[2];
    const float* jt_mess    =(const float*)d_in[3];
    const float* node_embed =(const float*)d_in[4];
    const float* node_mask  =(const float*)d_in[5];
    const float* edge_mask  =(const float*)d_in[6];
    const float* mes_w1     =(const float*)d_in[7];
    const float* mes_b1     =(const float*)d_in[8];
    const float* mes_w2     =(const float*)d_in[9];
    const float* mes_b2     =(const float*)d_in[10];
    const float* edge_w1    =(const float*)d_in[11];
    const float* edge_b1    =(const float*)d_in[12];
    const float* edge_w2    =(const float*)d_in[13];
    const float* edge_b2    =(const float*)d_in[14];
    const float* node_w1    =(const float*)d_in[15];
    const float* node_b1    =(const float*)d_in[16];
    const float* node_w2    =(const float*)d_in[17];
    const float* node_b2    =(const float*)d_in[18];
    const float* coord_w1   =(const float*)d_in[19];
    const float* coord_b1   =(const float*)d_in[20];
    const float* coord_w2   =(const float*)d_in[21];
    const int*   edge_index =(const int*)d_in[22];
    const int*   mess_holder=(const int*)d_in[23];
    const int*   node_holder=(const int*)d_in[24];
    const int*   jt_idx     =(const int*)d_in[25];

    float* outH=(float*)d_out;
    float* outC=outH+(size_t)NN*64;
    float* outE=outC+(size_t)NN*3;

    const int smemA=A_SMEMF*4, smemB=B_SMEMF*4, smemC=C_SMEMF*4;
    cudaFuncSetAttribute(kernel_prep, cudaFuncAttributeMaxDynamicSharedMemorySize,smemA);
    cudaFuncSetAttribute(kernel_edges,cudaFuncAttributeMaxDynamicSharedMemorySize,smemB);
    cudaFuncSetAttribute(kernel_nodes,cudaFuncAttributeMaxDynamicSharedMemorySize,smemC);

    kernel_prep<<<NN/128,256,smemA>>>(h,node_embed,mes_w1,node_holder,jt_idx);
    kernel_edges<<<148,TB,smemB>>>(coord,edge_attr,jt_mess,node_mask,edge_mask,
                                   mes_w1,mes_b1,mes_w2,mes_b2,
                                   edge_w1,edge_b1,edge_w2,edge_b2,
                                   coord_w1,coord_b1,coord_w2,
                                   edge_index+NE,mess_holder,jt_idx,outC,outE);
    kernel_nodes<<<NN/128,256,smemC>>>(node_w1,node_b1,node_w2,node_b2,node_mask,outH);
}

// round 14
// speedup vs baseline: 1.3583x; 1.3583x over previous
#include <cuda_runtime.h>
#include <cuda_bf16.h>
#include <math.h>
#include <stdint.h>

#define MAXA 54
#define NN   (1024*MAXA)
#define DEG  16
#define NE   (NN*DEG)
#define MMM  16
#define TILE_E 128
#define NTILES (NE/TILE_E)
#define NPT  (TILE_E/DEG)
#define STRIDE 68

typedef unsigned long long u64;
typedef unsigned int u32;

__device__ float g_h1 [(size_t)NN*64];
__device__ float g_P  [(size_t)NN*64];
__device__ float g_Q  [(size_t)NN*64];
__device__ float g_agg[(size_t)NN*64];

__device__ __forceinline__ u64 pk(float lo, float hi){u64 r;asm("mov.b64 %0,{%1,%2};":"=l"(r):"f"(lo),"f"(hi));return r;}
__device__ __forceinline__ void upk(u64 v,float&lo,float&hi){asm("mov.b64 {%0,%1},%2;":"=f"(lo),"=f"(hi):"l"(v));}
__device__ __forceinline__ void fma2(u64&d,u64 a,u64 b){asm("fma.rn.f32x2 %0,%1,%2,%0;":"+l"(d):"l"(a),"l"(b));}
__device__ __forceinline__ float silu(float x){return __fdividef(x, 1.f + __expf(-x));}
__device__ __forceinline__ void red2(float*p,float a,float b){
    asm volatile("red.global.add.v2.f32 [%0],{%1,%2};"::"l"(p),"f"(a),"f"(b):"memory");}
__device__ __forceinline__ u32 tf32c(float x){u32 r;asm("cvt.rna.tf32.f32 %0,%1;":"=r"(r):"f"(x));return r;}
__device__ __forceinline__ void mma8(float* c,u32 a0,u32 a1,u32 a2,u32 a3,u32 b0,u32 b1){
    asm("mma.sync.aligned.m16n8k8.row.col.f32.tf32.tf32.f32 "
        "{%0,%1,%2,%3},{%4,%5,%6,%7},{%8,%9},{%0,%1,%2,%3};"
        :"+f"(c[0]),"+f"(c[1]),"+f"(c[2]),"+f"(c[3])
        :"r"(a0),"r"(a1),"r"(a2),"r"(a3),"r"(b0),"r"(b1));
}

/* 3xTF32 warp GEMM round: D(16x32 per warp) += X(128xK=64 smem) @ Wfrag.
   W fragment-packed: W[g][k8][reg][lane] at ((g*8+k8)*2+reg)*32+lane. */
__device__ __forceinline__ void mma_round(const float* __restrict__ X,const float* __restrict__ W,
                                          int lane,int m0,int gbase,float acc[4][4]){
    const int r=m0+(lane>>2);
#pragma unroll
    for(int k8=0;k8<8;++k8){
        int kc=k8*8+(lane&3);
        float a0=X[r*STRIDE+kc],     a1=X[(r+8)*STRIDE+kc];
        float a2=X[r*STRIDE+kc+4],   a3=X[(r+8)*STRIDE+kc+4];
        u32 h0=tf32c(a0),h1=tf32c(a1),h2=tf32c(a2),h3=tf32c(a3);
        u32 l0=tf32c(a0-__uint_as_float(h0)), l1=tf32c(a1-__uint_as_float(h1));
        u32 l2=tf32c(a2-__uint_as_float(h2)), l3=tf32c(a3-__uint_as_float(h3));
#pragma unroll
        for(int nt=0;nt<4;++nt){
            const float* wp=W+((gbase+nt)*8+k8)*64;
            float b0=wp[lane], b1=wp[32+lane];
            u32 bh0=tf32c(b0), bh1=tf32c(b1);
            u32 bl0=tf32c(b0-__uint_as_float(bh0)), bl1=tf32c(b1-__uint_as_float(bh1));
            mma8(acc[nt],h0,h1,h2,h3,bh0,bh1);
            mma8(acc[nt],l0,l1,l2,l3,bh0,bh1);
            mma8(acc[nt],h0,h1,h2,h3,bl0,bl1);
        }
    }
}

/* ---- fp32 register GEMM for prep/nodes ---- */
template<int K>
__device__ __forceinline__ void gemm4(const float* __restrict__ X,const float* __restrict__ W,
                                      int ty,int c0,u64 acc[4][4]){
#pragma unroll 2
    for(int k4=0;k4<K/4;++k4){
        float4 xv[4];
#pragma unroll
        for(int i=0;i<4;++i) xv[i]=*(const float4*)(X+(ty*4+i)*STRIDE+k4*4);
#pragma unroll
        for(int kk=0;kk<4;++kk){
            const float* Wk=W+(k4*4+kk)*64;
            float4 wa=*(const float4*)(Wk+c0), wb=*(const float4*)(Wk+c0+32);
            u64 w0=pk(wa.x,wa.y),w1=pk(wa.z,wa.w),w2=pk(wb.x,wb.y),w3=pk(wb.z,wb.w);
#pragma unroll
            for(int i=0;i<4;++i){
                float x=(kk==0)?xv[i].x:(kk==1)?xv[i].y:(kk==2)?xv[i].z:xv[i].w;
                u64 xp=pk(x,x);
                fma2(acc[i][0],xp,w0);fma2(acc[i][1],xp,w1);
                fma2(acc[i][2],xp,w2);fma2(acc[i][3],xp,w3);
            }
        }
    }
}

/* =================== Kernel A: prep =================== */
#define A_W1A 0
#define A_W1B 4096
#define A_SH1 8192
#define A_SMEMF (8192+128*STRIDE)
__global__ void __launch_bounds__(256,1)
kernel_prep(const float* __restrict__ h,const float* __restrict__ node_embed,
            const float* __restrict__ mes_w1,const int* __restrict__ node_holder,
            const int* __restrict__ jt_idx){
    extern __shared__ float s[];
    const int tid=threadIdx.x, nb=blockIdx.x*128;
    for(int i=tid;i<4096;i+=256){s[A_W1A+i]=mes_w1[i];s[A_W1B+i]=mes_w1[4096+i];}
    for(int i=tid;i<128*64;i+=256){
        int l=i>>6,o=i&63,node=nb+l,cand=node/MAXA;
        int jn=node_holder[node],j=jt_idx[cand],jn1=jn>0?jn-1:0;
        float v=h[(size_t)node*64+o]+node_embed[((size_t)j*MMM+jn1)*64+o];
        s[A_SH1+l*STRIDE+o]=v; g_h1[(size_t)node*64+o]=v; g_agg[(size_t)node*64+o]=0.f;
    }
    __syncthreads();
    const int tx=tid&7, ty=tid>>3, c0=tx*4;
    u64 acc[4][4];
#pragma unroll
    for(int i=0;i<4;++i)
#pragma unroll
        for(int p=0;p<4;++p) acc[i][p]=0ull;
    gemm4<64>(s+A_SH1,s+A_W1A,ty,c0,acc);
#pragma unroll
    for(int i=0;i<4;++i){
        size_t b=(size_t)(nb+ty*4+i)*64; float v[8];
#pragma unroll
        for(int p=0;p<4;++p) upk(acc[i][p],v[2*p],v[2*p+1]);
        *(float4*)(g_P+b+c0)=make_float4(v[0],v[1],v[2],v[3]);
        *(float4*)(g_P+b+c0+32)=make_float4(v[4],v[5],v[6],v[7]);
    }
#pragma unroll
    for(int i=0;i<4;++i)
#pragma unroll
        for(int p=0;p<4;++p) acc[i][p]=0ull;
    gemm4<64>(s+A_SH1,s+A_W1B,ty,c0,acc);
#pragma unroll
    for(int i=0;i<4;++i){
        size_t b=(size_t)(nb+ty*4+i)*64; float v[8];
#pragma unroll
        for(int p=0;p<4;++p) upk(acc[i][p],v[2*p],v[2*p+1]);
        *(float4*)(g_Q+b+c0)=make_float4(v[0],v[1],v[2],v[3]);
        *(float4*)(g_Q+b+c0+32)=make_float4(v[4],v[5],v[6],v[7]);
    }
}

/* =================== Kernel B: edges (tf32 mma.sync) =================== */
#define WF      0               /* 6*4096 fragment-packed weights */
#define SB_B1   24576
#define SB_W1R  24640
#define SB_B2   24704
#define SB_CB1  24768
#define SB_CW2  24832
#define SB_EB1  24896
#define SB_EW1R 24960
#define SB_EB2  25024
#define BUFE    25088
#define BUFT    33792
#define BUFF    42496
#define SCOL    51200
#define SMB     51328
#define SEM     51456
#define SRAD    51584
#define SCD     51712
#define SGT     52096           /* 256 (two halves) */
#define STR     52352           /* 384 */
#define B_SMEMF 52736
#define TBE     512

__global__ void __launch_bounds__(TBE,1)
kernel_edges(const float* __restrict__ coord,const float* __restrict__ edge_attr,
             const float* __restrict__ jt_mess,const float* __restrict__ node_mask,
             const float* __restrict__ edge_mask,
             const float* __restrict__ mes_w1,const float* __restrict__ mes_b1,
             const float* __restrict__ mes_w2,const float* __restrict__ mes_b2,
             const float* __restrict__ edge_w1,const float* __restrict__ edge_b1,
             const float* __restrict__ edge_w2,const float* __restrict__ edge_b2,
             const float* __restrict__ coord_w1,const float* __restrict__ coord_b1,
             const float* __restrict__ coord_w2,
             const int* __restrict__ colidx,const int* __restrict__ mess_holder,
             const int* __restrict__ jt_idx,
             float* __restrict__ outC,float* __restrict__ outE){
    extern __shared__ float s[];
    int* scol=(int*)(s+SCOL); int* smb=(int*)(s+SMB);
    const int tid=threadIdx.x, wid=tid>>5, lane=tid&31;
    const int mrow=wid>>1, nhalf=wid&1;
    const int m0=mrow*16, gbase=nhalf*4;
    const int cb=nhalf*32+(lane&3)*2;   /* thread col base; +nt*8 */

    /* fragment-pack the 6 weight matrices */
    for(int idx=tid;idx<6*4096;idx+=TBE){
        int m=idx>>12, t=idx&4095, g=t>>9, k8=(t>>6)&7, rg=(t>>5)&1, ln=t&31;
        int k=k8*8+(ln&3)+rg*4, n=g*8+(ln>>2);
        const float* src=(m==0)?mes_w1+129*64:(m==1)?mes_w2:(m==2)?coord_w1
                        :(m==3)?edge_w1:(m==4)?edge_w1+65*64:edge_w2;
        s[WF+idx]=src[k*64+n];
    }
    if(tid<64){
        s[SB_B1+tid]=mes_b1[tid];   s[SB_W1R+tid]=mes_w1[128*64+tid];
        s[SB_B2+tid]=mes_b2[tid];   s[SB_CB1+tid]=coord_b1[tid];
        s[SB_CW2+tid]=coord_w2[tid];s[SB_EB1+tid]=edge_b1[tid];
        s[SB_EW1R+tid]=edge_w1[64*64+tid]; s[SB_EB2+tid]=edge_b2[tid];
    }
    __syncthreads();

    for(int tile=blockIdx.x;tile<NTILES;tile+=gridDim.x){
        const int e0=tile*TILE_E;

        if(tid<128){
            int ee=e0+tid, c=colidx[ee]; scol[tid]=c;
            int rr=ee>>4, cand=rr/MAXA, am=rr-cand*MAXA, ac=c-cand*MAXA;
            const int* jp=mess_holder+((((size_t)cand*MAXA+am)*MAXA+ac)<<1);
            int jr=jp[0],jc=jp[1],mb=-1;
            if(jr!=0&&jc!=0) mb=((jt_idx[cand]*MMM+(jr-1))*MMM+(jc-1))*64;
            smb[tid]=mb;
            s[SEM+tid]=edge_mask[ee];
            float dx=coord[rr*3+0]-coord[c*3+0];
            float dy=coord[rr*3+1]-coord[c*3+1];
            float dz=coord[rr*3+2]-coord[c*3+2];
            float rad=dx*dx+dy*dy+dz*dz; s[SRAD+tid]=rad;
            float inv=1.f/(sqrtf(rad+1e-8f)+1.f);
            s[SCD+tid*3+0]=dx*inv; s[SCD+tid*3+1]=dy*inv; s[SCD+tid*3+2]=dz*inv;
        }
        __syncthreads();

        const int r0=m0+(lane>>2), r1=r0+8;
        const int nrn=(e0+r0)>>4;
        const int col0=scol[r0], col1=scol[r1];

        /* prefetch P/Q pairs for this thread's 8 cols (in flight through staging+MMA1) */
        float2 Pv[4],Q0v[4],Q1v[4];
#pragma unroll
        for(int nt=0;nt<4;++nt){
            Pv[nt] =*(const float2*)(g_P+(size_t)nrn *64+cb+nt*8);
            Q0v[nt]=*(const float2*)(g_Q+(size_t)col0*64+cb+nt*8);
            Q1v[nt]=*(const float2*)(g_Q+(size_t)col1*64+cb+nt*8);
        }

        for(int idx=tid;idx<128*16;idx+=TBE){
            int e=idx>>4,o4=(idx&15)<<2;
            int eg=e0+e, mb=smb[e];
            float4 v=*(const float4*)(edge_attr+(size_t)eg*64+o4);
            if(mb>=0){ float4 m=*(const float4*)(jt_mess+(size_t)mb+o4);
                v.x+=m.x;v.y+=m.y;v.z+=m.z;v.w+=m.w; }
            *(float4*)(s+BUFE+e*STRIDE+o4)=v;
        }
        __syncthreads();

        float acc[4][4];
        const float rad0=s[SRAD+r0], rad1=s[SRAD+r1];
        const float em0=s[SEM+r0],  em1=s[SEM+r1];

        /* GEMM1: bufE@W1E + P + Q + rad*w1r + b1 ; silu -> bufT */
#pragma unroll
        for(int nt=0;nt<4;++nt){acc[nt][0]=acc[nt][1]=acc[nt][2]=acc[nt][3]=0.f;}
        mma_round(s+BUFE,s+WF+0*4096,lane,m0,gbase,acc);
#pragma unroll
        for(int nt=0;nt<4;++nt){
            int c=cb+nt*8;
            float2 bv=*(float2*)(s+SB_B1+c), wv=*(float2*)(s+SB_W1R+c);
            float2 o0,o1;
            o0.x=silu(acc[nt][0]+bv.x+rad0*wv.x+Pv[nt].x+Q0v[nt].x);
            o0.y=silu(acc[nt][1]+bv.y+rad0*wv.y+Pv[nt].y+Q0v[nt].y);
            o1.x=silu(acc[nt][2]+bv.x+rad1*wv.x+Pv[nt].x+Q1v[nt].x);
            o1.y=silu(acc[nt][3]+bv.y+rad1*wv.y+Pv[nt].y+Q1v[nt].y);
            *(float2*)(s+BUFT+r0*STRIDE+c)=o0;
            *(float2*)(s+BUFT+r1*STRIDE+c)=o1;
        }
        __syncthreads();

        /* GEMM2: bufT@W2 ; silu(+b2)*em -> bufF + agg red */
#pragma unroll
        for(int nt=0;nt<4;++nt){acc[nt][0]=acc[nt][1]=acc[nt][2]=acc[nt][3]=0.f;}
        mma_round(s+BUFT,s+WF+1*4096,lane,m0,gbase,acc);
#pragma unroll
        for(int nt=0;nt<4;++nt){
            int c=cb+nt*8;
            float2 bv=*(float2*)(s+SB_B2+c);
            float v0=silu(acc[nt][0]+bv.x)*em0, v1=silu(acc[nt][1]+bv.y)*em0;
            float v2=silu(acc[nt][2]+bv.x)*em1, v3=silu(acc[nt][3]+bv.y)*em1;
            *(float2*)(s+BUFF+r0*STRIDE+c)=make_float2(v0,v1);
            *(float2*)(s+BUFF+r1*STRIDE+c)=make_float2(v2,v3);
            red2(g_agg+(size_t)col0*64+c,v0,v1);
            red2(g_agg+(size_t)col1*64+c,v2,v3);
        }
        __syncthreads();

        /* GEMM3: coord gate */
#pragma unroll
        for(int nt=0;nt<4;++nt){acc[nt][0]=acc[nt][1]=acc[nt][2]=acc[nt][3]=0.f;}
        mma_round(s+BUFF,s+WF+2*4096,lane,m0,gbase,acc);
        {
            float pd0=0.f,pd1=0.f;
#pragma unroll
            for(int nt=0;nt<4;++nt){
                int c=cb+nt*8;
                float2 bv=*(float2*)(s+SB_CB1+c), cw=*(float2*)(s+SB_CW2+c);
                pd0+=silu(acc[nt][0]+bv.x)*cw.x+silu(acc[nt][1]+bv.y)*cw.y;
                pd1+=silu(acc[nt][2]+bv.x)*cw.x+silu(acc[nt][3]+bv.y)*cw.y;
            }
            pd0+=__shfl_xor_sync(0xffffffffu,pd0,1); pd0+=__shfl_xor_sync(0xffffffffu,pd0,2);
            pd1+=__shfl_xor_sync(0xffffffffu,pd1,1); pd1+=__shfl_xor_sync(0xffffffffu,pd1,2);
            if((lane&3)==0){ s[SGT+nhalf*128+r0]=pd0; s[SGT+nhalf*128+r1]=pd1; }
        }
        __syncthreads();
        if(tid<128){
            float g=(s[SGT+tid]+s[SGT+128+tid])*s[SEM+tid];
            s[STR+tid*3+0]=s[SCD+tid*3+0]*g;
            s[STR+tid*3+1]=s[SCD+tid*3+1]*g;
            s[STR+tid*3+2]=s[SCD+tid*3+2]*g;
        }
        __syncthreads();
        if(tid<NPT*3){
            int n=tid/3,c=tid-n*3; float sum=0.f;
#pragma unroll
            for(int k=0;k<DEG;++k) sum+=s[STR+(n*DEG+k)*3+c];
            int gn=tile*NPT+n;
            outC[gn*3+c]=(coord[gn*3+c]+sum)*node_mask[gn];
        }

        /* GEMM4: bufF@EW1A + bufE@EW1B ; silu(+eb1+rad*ew1r) -> bufT */
#pragma unroll
        for(int nt=0;nt<4;++nt){acc[nt][0]=acc[nt][1]=acc[nt][2]=acc[nt][3]=0.f;}
        mma_round(s+BUFF,s+WF+3*4096,lane,m0,gbase,acc);
        mma_round(s+BUFE,s+WF+4*4096,lane,m0,gbase,acc);
#pragma unroll
        for(int nt=0;nt<4;++nt){
            int c=cb+nt*8;
            float2 bv=*(float2*)(s+SB_EB1+c), wv=*(float2*)(s+SB_EW1R+c);
            float2 o0,o1;
            o0.x=silu(acc[nt][0]+bv.x+rad0*wv.x); o0.y=silu(acc[nt][1]+bv.y+rad0*wv.y);
            o1.x=silu(acc[nt][2]+bv.x+rad1*wv.x); o1.y=silu(acc[nt][3]+bv.y+rad1*wv.y);
            *(float2*)(s+BUFT+r0*STRIDE+c)=o0;
            *(float2*)(s+BUFT+r1*STRIDE+c)=o1;
        }
        __syncthreads();

        /* GEMM5: bufT@EW2 ; (+eb2)*em -> outE */
#pragma unroll
        for(int nt=0;nt<4;++nt){acc[nt][0]=acc[nt][1]=acc[nt][2]=acc[nt][3]=0.f;}
        mma_round(s+BUFT,s+WF+5*4096,lane,m0,gbase,acc);
#pragma unroll
        for(int nt=0;nt<4;++nt){
            int c=cb+nt*8;
            float2 bv=*(float2*)(s+SB_EB2+c);
            *(float2*)(outE+(size_t)(e0+r0)*64+c)=
                make_float2((acc[nt][0]+bv.x)*em0,(acc[nt][1]+bv.y)*em0);
            *(float2*)(outE+(size_t)(e0+r1)*64+c)=
                make_float2((acc[nt][2]+bv.x)*em1,(acc[nt][3]+bv.y)*em1);
        }
        __syncthreads();
    }
}

/* =================== Kernel C: node MLP =================== */
#define C_NW1 0
#define C_NW2 8192
#define C_NB1 12288
#define C_NB2 12352
#define C_BA  12416
#define C_BB  (12416+128*STRIDE)
#define C_BT  (12416+2*128*STRIDE)
#define C_SMEMF (12416+3*128*STRIDE)
__global__ void __launch_bounds__(256,1)
kernel_nodes(const float* __restrict__ node_w1,const float* __restrict__ node_b1,
             const float* __restrict__ node_w2,const float* __restrict__ node_b2,
             const float* __restrict__ node_mask,float* __restrict__ outH){
    extern __shared__ float s[];
    const int tid=threadIdx.x, nb=blockIdx.x*128;
    const int tx=tid&7, ty=tid>>3, c0=tx*4;
    for(int i=tid;i<8192;i+=256) s[C_NW1+i]=node_w1[i];
    for(int i=tid;i<4096;i+=256) s[C_NW2+i]=node_w2[i];
    if(tid<64){s[C_NB1+tid]=node_b1[tid];s[C_NB2+tid]=node_b2[tid];}
    for(int i=tid;i<128*16;i+=256){
        int l=i>>4,o4=(i&15)<<2; size_t b=(size_t)(nb+l)*64+o4;
        *(float4*)(s+C_BA+l*STRIDE+o4)=*(const float4*)(g_h1+b);
        *(float4*)(s+C_BB+l*STRIDE+o4)=*(const float4*)(g_agg+b);
    }
    __syncthreads();
    u64 acc[4][4];
#pragma unroll
    for(int i=0;i<4;++i){
        acc[i][0]=pk(s[C_NB1+c0],s[C_NB1+c0+1]);acc[i][1]=pk(s[C_NB1+c0+2],s[C_NB1+c0+3]);
        acc[i][2]=pk(s[C_NB1+c0+32],s[C_NB1+c0+33]);acc[i][3]=pk(s[C_NB1+c0+34],s[C_NB1+c0+35]);
    }
    gemm4<64>(s+C_BA,s+C_NW1,ty,c0,acc);
    gemm4<64>(s+C_BB,s+C_NW1+64*64,ty,c0,acc);
#pragma unroll
    for(int i=0;i<4;++i){
        float* d=s+C_BT+(ty*4+i)*STRIDE; float a,b;
        upk(acc[i][0],a,b);d[c0+0]=silu(a);d[c0+1]=silu(b);
        upk(acc[i][1],a,b);d[c0+2]=silu(a);d[c0+3]=silu(b);
        upk(acc[i][2],a,b);d[c0+32]=silu(a);d[c0+33]=silu(b);
        upk(acc[i][3],a,b);d[c0+34]=silu(a);d[c0+35]=silu(b);
    }
    __syncthreads();
#pragma unroll
    for(int i=0;i<4;++i){
        acc[i][0]=pk(s[C_NB2+c0],s[C_NB2+c0+1]);acc[i][1]=pk(s[C_NB2+c0+2],s[C_NB2+c0+3]);
        acc[i][2]=pk(s[C_NB2+c0+32],s[C_NB2+c0+33]);acc[i][3]=pk(s[C_NB2+c0+34],s[C_NB2+c0+35]);
    }
    gemm4<64>(s+C_BT,s+C_NW2,ty,c0,acc);
#pragma unroll
    for(int i=0;i<4;++i){
        int l=ty*4+i,node=nb+l; float nm=node_mask[node];
        const float* h1p=s+C_BA+l*STRIDE; float a,b,v0,v1,v2,v3;
        size_t base=(size_t)node*64;
        upk(acc[i][0],a,b);v0=(h1p[c0+0]+a)*nm;v1=(h1p[c0+1]+b)*nm;
        upk(acc[i][1],a,b);v2=(h1p[c0+2]+a)*nm;v3=(h1p[c0+3]+b)*nm;
        *(float4*)(outH+base+c0)=make_float4(v0,v1,v2,v3);
        upk(acc[i][2],a,b);v0=(h1p[c0+32]+a)*nm;v1=(h1p[c0+33]+b)*nm;
        upk(acc[i][3],a,b);v2=(h1p[c0+34]+a)*nm;v3=(h1p[c0+35]+b)*nm;
        *(float4*)(outH+base+c0+32)=make_float4(v0,v1,v2,v3);
    }
}

/* =================== launcher =================== */
extern "C" void kernel_launch(void* const* d_in, const int* in_sizes, int n_in,
                              void* d_out, int out_size)
{
    const float* h          =(const float*)d_in[0];
    const float* coord      =(const float*)d_in[1];
    const float* edge_attr  =(const float*)d_in[2];
    const float* jt_mess    =(const float*)d_in[3];
    const float* node_embed =(const float*)d_in[4];
    const float* node_mask  =(const float*)d_in[5];
    const float* edge_mask  =(const float*)d_in[6];
    const float* mes_w1     =(const float*)d_in[7];
    const float* mes_b1     =(const float*)d_in[8];
    const float* mes_w2     =(const float*)d_in[9];
    const float* mes_b2     =(const float*)d_in[10];
    const float* edge_w1    =(const float*)d_in[11];
    const float* edge_b1    =(const float*)d_in[12];
    const float* edge_w2    =(const float*)d_in[13];
    const float* edge_b2    =(const float*)d_in[14];
    const float* node_w1    =(const float*)d_in[15];
    const float* node_b1    =(const float*)d_in[16];
    const float* node_w2    =(const float*)d_in[17];
    const float* node_b2    =(const float*)d_in[18];
    const float* coord_w1   =(const float*)d_in[19];
    const float* coord_b1   =(const float*)d_in[20];
    const float* coord_w2   =(const float*)d_in[21];
    const int*   edge_index =(const int*)d_in[22];
    const int*   mess_holder=(const int*)d_in[23];
    const int*   node_holder=(const int*)d_in[24];
    const int*   jt_idx     =(const int*)d_in[25];

    float* outH=(float*)d_out;
    float* outC=outH+(size_t)NN*64;
    float* outE=outC+(size_t)NN*3;

    const int smemA=A_SMEMF*4, smemB=B_SMEMF*4, smemC=C_SMEMF*4;
    cudaFuncSetAttribute(kernel_prep, cudaFuncAttributeMaxDynamicSharedMemorySize,smemA);
    cudaFuncSetAttribute(kernel_edges,cudaFuncAttributeMaxDynamicSharedMemorySize,smemB);
    cudaFuncSetAttribute(kernel_nodes,cudaFuncAttributeMaxDynamicSharedMemorySize,smemC);

    kernel_prep<<<NN/128,256,smemA>>>(h,node_embed,mes_w1,node_holder,jt_idx);
    kernel_edges<<<148,TBE,smemB>>>(coord,edge_attr,jt_mess,node_mask,edge_mask,
                                    mes_w1,mes_b1,mes_w2,mes_b2,
                                    edge_w1,edge_b1,edge_w2,edge_b2,
                                    coord_w1,coord_b1,coord_w2,
                                    edge_index+NE,mess_holder,jt_idx,outC,outE);
    kernel_nodes<<<NN/128,256,smemC>>>(node_w1,node_b1,node_w2,node_b2,node_mask,outH);
}

// round 15
// speedup vs baseline: 1.4315x; 1.0539x over previous
#include <cuda_runtime.h>
#include <cuda_bf16.h>
#include <math.h>
#include <stdint.h>

#define MAXA 54
#define NN   (1024*MAXA)
#define DEG  16
#define NE   (NN*DEG)
#define MMM  16
#define TILE_E 128
#define NTILES (NE/TILE_E)
#define NPT  (TILE_E/DEG)
#define STRIDE 68

typedef unsigned long long u64;
typedef unsigned int u32;

__device__ float g_h1 [(size_t)NN*64];
__device__ float g_P  [(size_t)NN*64];
__device__ float g_Q  [(size_t)NN*64];
__device__ float g_agg[(size_t)NN*64];

__device__ __forceinline__ u64 pk(float lo, float hi){u64 r;asm("mov.b64 %0,{%1,%2};":"=l"(r):"f"(lo),"f"(hi));return r;}
__device__ __forceinline__ void upk(u64 v,float&lo,float&hi){asm("mov.b64 {%0,%1},%2;":"=f"(lo),"=f"(hi):"l"(v));}
__device__ __forceinline__ void fma2(u64&d,u64 a,u64 b){asm("fma.rn.f32x2 %0,%1,%2,%0;":"+l"(d):"l"(a),"l"(b));}
__device__ __forceinline__ float silu(float x){return __fdividef(x, 1.f + __expf(-x));}
__device__ __forceinline__ void red2(float*p,float a,float b){
    asm volatile("red.global.add.v2.f32 [%0],{%1,%2};"::"l"(p),"f"(a),"f"(b):"memory");}
__device__ __forceinline__ u32 prmt7632(u32 a,u32 b){u32 d;asm("prmt.b32 %0,%1,%2,0x7632;":"=r"(d):"r"(a),"r"(b));return d;}
__device__ __forceinline__ u32 cvt2(float hi,float lo){u32 d;asm("cvt.rn.bf16x2.f32 %0,%1,%2;":"=r"(d):"f"(hi),"f"(lo));return d;}
__device__ __forceinline__ float trunchi(float x){return __uint_as_float(__float_as_uint(x)&0xffff0000u);}
__device__ __forceinline__ void mmab(float* c,u32 a0,u32 a1,u32 a2,u32 a3,u32 b0,u32 b1){
    asm("mma.sync.aligned.m16n8k16.row.col.f32.bf16.bf16.f32 "
        "{%0,%1,%2,%3},{%4,%5,%6,%7},{%8,%9},{%0,%1,%2,%3};"
        :"+f"(c[0]),"+f"(c[1]),"+f"(c[2]),"+f"(c[3])
        :"r"(a0),"r"(a1),"r"(a2),"r"(a3),"r"(b0),"r"(b1));
}

/* bf16 split-P warp GEMM round: D(16x32 per warp) += X(128x64 smem) @ W.
   Whi/Wlo fragment-packed u32: [g][k16][reg][lane] at ((g*4+k16)*2+reg)*32+lane,
   lo block at +2048. P=3: AhiBhi+AloBhi+AhiBlo; P=1: AhiBhi. */
template<int P>
__device__ __forceinline__ void mma_round(const float* __restrict__ X,const u32* __restrict__ Whi,
                                          int lane,int m0,int gbase,float acc[4][4]){
    const int r0=m0+(lane>>2);
    const u32* Wlo=Whi+2048;
#pragma unroll
    for(int k16=0;k16<4;++k16){
        int kc=k16*16+(lane&3)*2;
        float2 p0=*(const float2*)(X+r0*STRIDE+kc);
        float2 p1=*(const float2*)(X+(r0+8)*STRIDE+kc);
        float2 p2=*(const float2*)(X+r0*STRIDE+kc+8);
        float2 p3=*(const float2*)(X+(r0+8)*STRIDE+kc+8);
        u32 ah0=prmt7632(__float_as_uint(p0.x),__float_as_uint(p0.y));
        u32 ah1=prmt7632(__float_as_uint(p1.x),__float_as_uint(p1.y));
        u32 ah2=prmt7632(__float_as_uint(p2.x),__float_as_uint(p2.y));
        u32 ah3=prmt7632(__float_as_uint(p3.x),__float_as_uint(p3.y));
        u32 al0=0,al1=0,al2=0,al3=0;
        if(P>=2){
            al0=cvt2(p0.y-trunchi(p0.y), p0.x-trunchi(p0.x));
            al1=cvt2(p1.y-trunchi(p1.y), p1.x-trunchi(p1.x));
            al2=cvt2(p2.y-trunchi(p2.y), p2.x-trunchi(p2.x));
            al3=cvt2(p3.y-trunchi(p3.y), p3.x-trunchi(p3.x));
        }
#pragma unroll
        for(int nt=0;nt<4;++nt){
            int base=((gbase+nt)*4+k16)*64+lane;
            u32 bh0=Whi[base], bh1=Whi[base+32];
            mmab(acc[nt],ah0,ah1,ah2,ah3,bh0,bh1);
            if(P>=2) mmab(acc[nt],al0,al1,al2,al3,bh0,bh1);
            if(P>=3){ u32 bl0=Wlo[base], bl1=Wlo[base+32];
                      mmab(acc[nt],ah0,ah1,ah2,ah3,bl0,bl1); }
        }
    }
}

/* ---- fp32 register GEMM for prep/nodes ---- */
template<int K>
__device__ __forceinline__ void gemm4(const float* __restrict__ X,const float* __restrict__ W,
                                      int ty,int c0,u64 acc[4][4]){
#pragma unroll 2
    for(int k4=0;k4<K/4;++k4){
        float4 xv[4];
#pragma unroll
        for(int i=0;i<4;++i) xv[i]=*(const float4*)(X+(ty*4+i)*STRIDE+k4*4);
#pragma unroll
        for(int kk=0;kk<4;++kk){
            const float* Wk=W+(k4*4+kk)*64;
            float4 wa=*(const float4*)(Wk+c0), wb=*(const float4*)(Wk+c0+32);
            u64 w0=pk(wa.x,wa.y),w1=pk(wa.z,wa.w),w2=pk(wb.x,wb.y),w3=pk(wb.z,wb.w);
#pragma unroll
            for(int i=0;i<4;++i){
                float x=(kk==0)?xv[i].x:(kk==1)?xv[i].y:(kk==2)?xv[i].z:xv[i].w;
                u64 xp=pk(x,x);
                fma2(acc[i][0],xp,w0);fma2(acc[i][1],xp,w1);
                fma2(acc[i][2],xp,w2);fma2(acc[i][3],xp,w3);
            }
        }
    }
}

/* =================== Kernel A: prep =================== */
#define A_W1A 0
#define A_W1B 4096
#define A_SH1 8192
#define A_SMEMF (8192+128*STRIDE)
__global__ void __launch_bounds__(256,1)
kernel_prep(const float* __restrict__ h,const float* __restrict__ node_embed,
            const float* __restrict__ mes_w1,const int* __restrict__ node_holder,
            const int* __restrict__ jt_idx){
    extern __shared__ float s[];
    const int tid=threadIdx.x, nb=blockIdx.x*128;
    for(int i=tid;i<4096;i+=256){s[A_W1A+i]=mes_w1[i];s[A_W1B+i]=mes_w1[4096+i];}
    for(int i=tid;i<128*64;i+=256){
        int l=i>>6,o=i&63,node=nb+l,cand=node/MAXA;
        int jn=node_holder[node],j=jt_idx[cand],jn1=jn>0?jn-1:0;
        float v=h[(size_t)node*64+o]+node_embed[((size_t)j*MMM+jn1)*64+o];
        s[A_SH1+l*STRIDE+o]=v; g_h1[(size_t)node*64+o]=v; g_agg[(size_t)node*64+o]=0.f;
    }
    __syncthreads();
    const int tx=tid&7, ty=tid>>3, c0=tx*4;
    u64 acc[4][4];
#pragma unroll
    for(int i=0;i<4;++i)
#pragma unroll
        for(int p=0;p<4;++p) acc[i][p]=0ull;
    gemm4<64>(s+A_SH1,s+A_W1A,ty,c0,acc);
#pragma unroll
    for(int i=0;i<4;++i){
        size_t b=(size_t)(nb+ty*4+i)*64; float v[8];
#pragma unroll
        for(int p=0;p<4;++p) upk(acc[i][p],v[2*p],v[2*p+1]);
        *(float4*)(g_P+b+c0)=make_float4(v[0],v[1],v[2],v[3]);
        *(float4*)(g_P+b+c0+32)=make_float4(v[4],v[5],v[6],v[7]);
    }
#pragma unroll
    for(int i=0;i<4;++i)
#pragma unroll
        for(int p=0;p<4;++p) acc[i][p]=0ull;
    gemm4<64>(s+A_SH1,s+A_W1B,ty,c0,acc);
#pragma unroll
    for(int i=0;i<4;++i){
        size_t b=(size_t)(nb+ty*4+i)*64; float v[8];
#pragma unroll
        for(int p=0;p<4;++p) upk(acc[i][p],v[2*p],v[2*p+1]);
        *(float4*)(g_Q+b+c0)=make_float4(v[0],v[1],v[2],v[3]);
        *(float4*)(g_Q+b+c0+32)=make_float4(v[4],v[5],v[6],v[7]);
    }
}

/* =================== Kernel B: edges (bf16x3 mma.sync) =================== */
#define WF      0               /* 6*4096: per matrix 2048 u32 hi + 2048 u32 lo */
#define SB_B1   24576
#define SB_W1R  24640
#define SB_B2   24704
#define SB_CB1  24768
#define SB_CW2  24832
#define SB_EB1  24896
#define SB_EW1R 24960
#define SB_EB2  25024
#define BUFE    25088
#define BUFT    33792
#define BUFF    42496
#define SCOL    51200
#define SMB     51328
#define SEM     51456
#define SRAD    51584
#define SCD     51712
#define SGT     52096
#define STR     52352
#define B_SMEMF 52736
#define TBE     512

__global__ void __launch_bounds__(TBE,1)
kernel_edges(const float* __restrict__ coord,const float* __restrict__ edge_attr,
             const float* __restrict__ jt_mess,const float* __restrict__ node_mask,
             const float* __restrict__ edge_mask,
             const float* __restrict__ mes_w1,const float* __restrict__ mes_b1,
             const float* __restrict__ mes_w2,const float* __restrict__ mes_b2,
             const float* __restrict__ edge_w1,const float* __restrict__ edge_b1,
             const float* __restrict__ edge_w2,const float* __restrict__ edge_b2,
             const float* __restrict__ coord_w1,const float* __restrict__ coord_b1,
             const float* __restrict__ coord_w2,
             const int* __restrict__ colidx,const int* __restrict__ mess_holder,
             const int* __restrict__ jt_idx,
             float* __restrict__ outC,float* __restrict__ outE){
    extern __shared__ float s[];
    int* scol=(int*)(s+SCOL); int* smb=(int*)(s+SMB);
    u32* wfrag=(u32*)(s+WF);
    const int tid=threadIdx.x, wid=tid>>5, lane=tid&31;
    const int mrow=wid>>1, nhalf=wid&1;
    const int m0=mrow*16, gbase=nhalf*4;
    const int cb=nhalf*32+(lane&3)*2;

    /* pack 6 weight matrices as bf16 hi/lo fragments */
    for(int idx=tid;idx<6*4096;idx+=TBE){
        int m=idx>>12, t=idx&4095, hl=t>>11, rest=t&2047;
        int g=rest>>8, k16=(rest>>6)&3, rg=(rest>>5)&1, ln=rest&31;
        int n=g*8+(ln>>2), k0=k16*16+(ln&3)*2+rg*8;
        const float* src=(m==0)?mes_w1+129*64:(m==1)?mes_w2:(m==2)?coord_w1
                        :(m==3)?edge_w1:(m==4)?edge_w1+65*64:edge_w2;
        float w0=src[k0*64+n], w1=src[(k0+1)*64+n];
        u32 v;
        if(hl==0) v=prmt7632(__float_as_uint(w0),__float_as_uint(w1));
        else      v=cvt2(w1-trunchi(w1), w0-trunchi(w0));
        wfrag[m*4096+hl*2048+rest]=v;
    }
    if(tid<64){
        s[SB_B1+tid]=mes_b1[tid];   s[SB_W1R+tid]=mes_w1[128*64+tid];
        s[SB_B2+tid]=mes_b2[tid];   s[SB_CB1+tid]=coord_b1[tid];
        s[SB_CW2+tid]=coord_w2[tid];s[SB_EB1+tid]=edge_b1[tid];
        s[SB_EW1R+tid]=edge_w1[64*64+tid]; s[SB_EB2+tid]=edge_b2[tid];
    }
    __syncthreads();

    for(int tile=blockIdx.x;tile<NTILES;tile+=gridDim.x){
        const int e0=tile*TILE_E;

        if(tid<128){
            int ee=e0+tid, c=colidx[ee]; scol[tid]=c;
            int rr=ee>>4, cand=rr/MAXA, am=rr-cand*MAXA, ac=c-cand*MAXA;
            const int* jp=mess_holder+((((size_t)cand*MAXA+am)*MAXA+ac)<<1);
            int jr=jp[0],jc=jp[1],mb=-1;
            if(jr!=0&&jc!=0) mb=((jt_idx[cand]*MMM+(jr-1))*MMM+(jc-1))*64;
            smb[tid]=mb;
            s[SEM+tid]=edge_mask[ee];
            float dx=coord[rr*3+0]-coord[c*3+0];
            float dy=coord[rr*3+1]-coord[c*3+1];
            float dz=coord[rr*3+2]-coord[c*3+2];
            float rad=dx*dx+dy*dy+dz*dz; s[SRAD+tid]=rad;
            float inv=1.f/(sqrtf(rad+1e-8f)+1.f);
            s[SCD+tid*3+0]=dx*inv; s[SCD+tid*3+1]=dy*inv; s[SCD+tid*3+2]=dz*inv;
        }
        __syncthreads();

        const int r0=m0+(lane>>2), r1=r0+8;
        const int nrn=(e0+r0)>>4;
        const int col0=scol[r0], col1=scol[r1];

        float2 Pv[4],Q0v[4],Q1v[4];
#pragma unroll
        for(int nt=0;nt<4;++nt){
            Pv[nt] =*(const float2*)(g_P+(size_t)nrn *64+cb+nt*8);
            Q0v[nt]=*(const float2*)(g_Q+(size_t)col0*64+cb+nt*8);
            Q1v[nt]=*(const float2*)(g_Q+(size_t)col1*64+cb+nt*8);
        }

        for(int idx=tid;idx<128*16;idx+=TBE){
            int e=idx>>4,o4=(idx&15)<<2;
            int eg=e0+e, mb=smb[e];
            float4 v=*(const float4*)(edge_attr+(size_t)eg*64+o4);
            if(mb>=0){ float4 m=*(const float4*)(jt_mess+(size_t)mb+o4);
                v.x+=m.x;v.y+=m.y;v.z+=m.z;v.w+=m.w; }
            *(float4*)(s+BUFE+e*STRIDE+o4)=v;
        }
        __syncthreads();

        float acc[4][4];
        const float rad0=s[SRAD+r0], rad1=s[SRAD+r1];
        const float em0=s[SEM+r0],  em1=s[SEM+r1];

        /* GEMM1: bufE@W1E + P + Q + rad*w1r + b1 ; silu -> bufT */
#pragma unroll
        for(int nt=0;nt<4;++nt){acc[nt][0]=acc[nt][1]=acc[nt][2]=acc[nt][3]=0.f;}
        mma_round<3>(s+BUFE,wfrag+0*4096,lane,m0,gbase,acc);
#pragma unroll
        for(int nt=0;nt<4;++nt){
            int c=cb+nt*8;
            float2 bv=*(float2*)(s+SB_B1+c), wv=*(float2*)(s+SB_W1R+c);
            float2 o0,o1;
            o0.x=silu(acc[nt][0]+bv.x+rad0*wv.x+Pv[nt].x+Q0v[nt].x);
            o0.y=silu(acc[nt][1]+bv.y+rad0*wv.y+Pv[nt].y+Q0v[nt].y);
            o1.x=silu(acc[nt][2]+bv.x+rad1*wv.x+Pv[nt].x+Q1v[nt].x);
            o1.y=silu(acc[nt][3]+bv.y+rad1*wv.y+Pv[nt].y+Q1v[nt].y);
            *(float2*)(s+BUFT+r0*STRIDE+c)=o0;
            *(float2*)(s+BUFT+r1*STRIDE+c)=o1;
        }
        __syncthreads();

        /* GEMM2: bufT@W2 ; silu(+b2)*em -> bufF + agg red */
#pragma unroll
        for(int nt=0;nt<4;++nt){acc[nt][0]=acc[nt][1]=acc[nt][2]=acc[nt][3]=0.f;}
        mma_round<3>(s+BUFT,wfrag+1*4096,lane,m0,gbase,acc);
#pragma unroll
        for(int nt=0;nt<4;++nt){
            int c=cb+nt*8;
            float2 bv=*(float2*)(s+SB_B2+c);
            float v0=silu(acc[nt][0]+bv.x)*em0, v1=silu(acc[nt][1]+bv.y)*em0;
            float v2=silu(acc[nt][2]+bv.x)*em1, v3=silu(acc[nt][3]+bv.y)*em1;
            *(float2*)(s+BUFF+r0*STRIDE+c)=make_float2(v0,v1);
            *(float2*)(s+BUFF+r1*STRIDE+c)=make_float2(v2,v3);
            red2(g_agg+(size_t)col0*64+c,v0,v1);
            red2(g_agg+(size_t)col1*64+c,v2,v3);
        }
        __syncthreads();

        /* GEMM3: coord gate (1-pass bf16 — feeds only the tiny coord delta) */
#pragma unroll
        for(int nt=0;nt<4;++nt){acc[nt][0]=acc[nt][1]=acc[nt][2]=acc[nt][3]=0.f;}
        mma_round<1>(s+BUFF,wfrag+2*4096,lane,m0,gbase,acc);
        {
            float pd0=0.f,pd1=0.f;
#pragma unroll
            for(int nt=0;nt<4;++nt){
                int c=cb+nt*8;
                float2 bv=*(float2*)(s+SB_CB1+c), cw=*(float2*)(s+SB_CW2+c);
                pd0+=silu(acc[nt][0]+bv.x)*cw.x+silu(acc[nt][1]+bv.y)*cw.y;
                pd1+=silu(acc[nt][2]+bv.x)*cw.x+silu(acc[nt][3]+bv.y)*cw.y;
            }
            pd0+=__shfl_xor_sync(0xffffffffu,pd0,1); pd0+=__shfl_xor_sync(0xffffffffu,pd0,2);
            pd1+=__shfl_xor_sync(0xffffffffu,pd1,1); pd1+=__shfl_xor_sync(0xffffffffu,pd1,2);
            if((lane&3)==0){ s[SGT+nhalf*128+r0]=pd0; s[SGT+nhalf*128+r1]=pd1; }
        }
        __syncthreads();
        if(tid<128){
            float g=(s[SGT+tid]+s[SGT+128+tid])*s[SEM+tid];
            s[STR+tid*3+0]=s[SCD+tid*3+0]*g;
            s[STR+tid*3+1]=s[SCD+tid*3+1]*g;
            s[STR+tid*3+2]=s[SCD+tid*3+2]*g;
        }
        __syncthreads();
        if(tid<NPT*3){
            int n=tid/3,c=tid-n*3; float sum=0.f;
#pragma unroll
            for(int k=0;k<DEG;++k) sum+=s[STR+(n*DEG+k)*3+c];
            int gn=tile*NPT+n;
            outC[gn*3+c]=(coord[gn*3+c]+sum)*node_mask[gn];
        }

        /* GEMM4: bufF@EW1A + bufE@EW1B ; silu(+eb1+rad*ew1r) -> bufT */
#pragma unroll
        for(int nt=0;nt<4;++nt){acc[nt][0]=acc[nt][1]=acc[nt][2]=acc[nt][3]=0.f;}
        mma_round<3>(s+BUFF,wfrag+3*4096,lane,m0,gbase,acc);
        mma_round<3>(s+BUFE,wfrag+4*4096,lane,m0,gbase,acc);
#pragma unroll
        for(int nt=0;nt<4;++nt){
            int c=cb+nt*8;
            float2 bv=*(float2*)(s+SB_EB1+c), wv=*(float2*)(s+SB_EW1R+c);
            float2 o0,o1;
            o0.x=silu(acc[nt][0]+bv.x+rad0*wv.x); o0.y=silu(acc[nt][1]+bv.y+rad0*wv.y);
            o1.x=silu(acc[nt][2]+bv.x+rad1*wv.x); o1.y=silu(acc[nt][3]+bv.y+rad1*wv.y);
            *(float2*)(s+BUFT+r0*STRIDE+c)=o0;
            *(float2*)(s+BUFT+r1*STRIDE+c)=o1;
        }
        __syncthreads();

        /* GEMM5: bufT@EW2 ; (+eb2)*em -> outE */
#pragma unroll
        for(int nt=0;nt<4;++nt){acc[nt][0]=acc[nt][1]=acc[nt][2]=acc[nt][3]=0.f;}
        mma_round<3>(s+BUFT,wfrag+5*4096,lane,m0,gbase,acc);
#pragma unroll
        for(int nt=0;nt<4;++nt){
            int c=cb+nt*8;
            float2 bv=*(float2*)(s+SB_EB2+c);
            *(float2*)(outE+(size_t)(e0+r0)*64+c)=
                make_float2((acc[nt][0]+bv.x)*em0,(acc[nt][1]+bv.y)*em0);
            *(float2*)(outE+(size_t)(e0+r1)*64+c)=
                make_float2((acc[nt][2]+bv.x)*em1,(acc[nt][3]+bv.y)*em1);
        }
        __syncthreads();
    }
}

/* =================== Kernel C: node MLP =================== */
#define C_NW1 0
#define C_NW2 8192
#define C_NB1 12288
#define C_NB2 12352
#define C_BA  12416
#define C_BB  (12416+128*STRIDE)
#define C_BT  (12416+2*128*STRIDE)
#define C_SMEMF (12416+3*128*STRIDE)
__global__ void __launch_bounds__(256,1)
kernel_nodes(const float* __restrict__ node_w1,const float* __restrict__ node_b1,
             const float* __restrict__ node_w2,const float* __restrict__ node_b2,
             const float* __restrict__ node_mask,float* __restrict__ outH){
    extern __shared__ float s[];
    const int tid=threadIdx.x, nb=blockIdx.x*128;
    const int tx=tid&7, ty=tid>>3, c0=tx*4;
    for(int i=tid;i<8192;i+=256) s[C_NW1+i]=node_w1[i];
    for(int i=tid;i<4096;i+=256) s[C_NW2+i]=node_w2[i];
    if(tid<64){s[C_NB1+tid]=node_b1[tid];s[C_NB2+tid]=node_b2[tid];}
    for(int i=tid;i<128*16;i+=256){
        int l=i>>4,o4=(i&15)<<2; size_t b=(size_t)(nb+l)*64+o4;
        *(float4*)(s+C_BA+l*STRIDE+o4)=*(const float4*)(g_h1+b);
        *(float4*)(s+C_BB+l*STRIDE+o4)=*(const float4*)(g_agg+b);
    }
    __syncthreads();
    u64 acc[4][4];
#pragma unroll
    for(int i=0;i<4;++i){
        acc[i][0]=pk(s[C_NB1+c0],s[C_NB1+c0+1]);acc[i][1]=pk(s[C_NB1+c0+2],s[C_NB1+c0+3]);
        acc[i][2]=pk(s[C_NB1+c0+32],s[C_NB1+c0+33]);acc[i][3]=pk(s[C_NB1+c0+34],s[C_NB1+c0+35]);
    }
    gemm4<64>(s+C_BA,s+C_NW1,ty,c0,acc);
    gemm4<64>(s+C_BB,s+C_NW1+64*64,ty,c0,acc);
#pragma unroll
    for(int i=0;i<4;++i){
        float* d=s+C_BT+(ty*4+i)*STRIDE; float a,b;
        upk(acc[i][0],a,b);d[c0+0]=silu(a);d[c0+1]=silu(b);
        upk(acc[i][1],a,b);d[c0+2]=silu(a);d[c0+3]=silu(b);
        upk(acc[i][2],a,b);d[c0+32]=silu(a);d[c0+33]=silu(b);
        upk(acc[i][3],a,b);d[c0+34]=silu(a);d[c0+35]=silu(b);
    }
    __syncthreads();
#pragma unroll
    for(int i=0;i<4;++i){
        acc[i][0]=pk(s[C_NB2+c0],s[C_NB2+c0+1]);acc[i][1]=pk(s[C_NB2+c0+2],s[C_NB2+c0+3]);
        acc[i][2]=pk(s[C_NB2+c0+32],s[C_NB2+c0+33]);acc[i][3]=pk(s[C_NB2+c0+34],s[C_NB2+c0+35]);
    }
    gemm4<64>(s+C_BT,s+C_NW2,ty,c0,acc);
#pragma unroll
    for(int i=0;i<4;++i){
        int l=ty*4+i,node=nb+l; float nm=node_mask[node];
        const float* h1p=s+C_BA+l*STRIDE; float a,b,v0,v1,v2,v3;
        size_t base=(size_t)node*64;
        upk(acc[i][0],a,b);v0=(h1p[c0+0]+a)*nm;v1=(h1p[c0+1]+b)*nm;
        upk(acc[i][1],a,b);v2=(h1p[c0+2]+a)*nm;v3=(h1p[c0+3]+b)*nm;
        *(float4*)(outH+base+c0)=make_float4(v0,v1,v2,v3);
        upk(acc[i][2],a,b);v0=(h1p[c0+32]+a)*nm;v1=(h1p[c0+33]+b)*nm;
        upk(acc[i][3],a,b);v2=(h1p[c0+34]+a)*nm;v3=(h1p[c0+35]+b)*nm;
        *(float4*)(outH+base+c0+32)=make_float4(v0,v1,v2,v3);
    }
}

/* =================== launcher =================== */
extern "C" void kernel_launch(void* const* d_in, const int* in_sizes, int n_in,
                              void* d_out, int out_size)
{
    const float* h          =(const float*)d_in[0];
    const float* coord      =(const float*)d_in[1];
    const float* edge_attr  =(const float*)d_in[2];
    const float* jt_mess    =(const float*)d_in[3];
    const float* node_embed =(const float*)d_in[4];
    const float* node_mask  =(const float*)d_in[5];
    const float* edge_mask  =(const float*)d_in[6];
    const float* mes_w1     =(const float*)d_in[7];
    const float* mes_b1     =(const float*)d_in[8];
    const float* mes_w2     =(const float*)d_in[9];
    const float* mes_b2     =(const float*)d_in[10];
    const float* edge_w1    =(const float*)d_in[11];
    const float* edge_b1    =(const float*)d_in[12];
    const float* edge_w2    =(const float*)d_in[13];
    const float* edge_b2    =(const float*)d_in[14];
    const float* node_w1    =(const float*)d_in[15];
    const float* node_b1    =(const float*)d_in[16];
    const float* node_w2    =(const float*)d_in[17];
    const float* node_b2    =(const float*)d_in[18];
    const float* coord_w1   =(const float*)d_in[19];
    const float* coord_b1   =(const float*)d_in[20];
    const float* coord_w2   =(const float*)d_in[21];
    const int*   edge_index =(const int*)d_in[22];
    const int*   mess_holder=(const int*)d_in[23];
    const int*   node_holder=(const int*)d_in[24];
    const int*   jt_idx     =(const int*)d_in[25];

    float* outH=(float*)d_out;
    float* outC=outH+(size_t)NN*64;
    float* outE=outC+(size_t)NN*3;

    const int smemA=A_SMEMF*4, smemB=B_SMEMF*4, smemC=C_SMEMF*4;
    cudaFuncSetAttribute(kernel_prep, cudaFuncAttributeMaxDynamicSharedMemorySize,smemA);
    cudaFuncSetAttribute(kernel_edges,cudaFuncAttributeMaxDynamicSharedMemorySize,smemB);
    cudaFuncSetAttribute(kernel_nodes,cudaFuncAttributeMaxDynamicSharedMemorySize,smemC);

    kernel_prep<<<NN/128,256,smemA>>>(h,node_embed,mes_w1,node_holder,jt_idx);
    kernel_edges<<<148,TBE,smemB>>>(coord,edge_attr,jt_mess,node_mask,edge_mask,
                                    mes_w1,mes_b1,mes_w2,mes_b2,
                                    edge_w1,edge_b1,edge_w2,edge_b2,
                                    coord_w1,coord_b1,coord_w2,
                                    edge_index+NE,mess_holder,jt_idx,outC,outE);
    kernel_nodes<<<NN/128,256,smemC>>>(node_w1,node_b1,node_w2,node_b2,node_mask,outH);
}

// round 16
// speedup vs baseline: 1.7696x; 1.2362x over previous
#include <cuda_runtime.h>
#include <cuda_bf16.h>
#include <math.h>
#include <stdint.h>

#define MAXA 54
#define NN   (1024*MAXA)
#define DEG  16
#define NE   (NN*DEG)
#define MMM  16
#define TILE_E 128
#define NTILES (NE/TILE_E)
#define NPT  (TILE_E/DEG)
#define STRIDE 68
#define PLANE 4352            /* 128*34 u32 per plane */

typedef unsigned long long u64;
typedef unsigned int u32;

__device__ float g_h1 [(size_t)NN*64];
__device__ float g_P  [(size_t)NN*64];
__device__ float g_Q  [(size_t)NN*64];
__device__ float g_agg[(size_t)NN*64];

__device__ __forceinline__ u64 pk(float lo, float hi){u64 r;asm("mov.b64 %0,{%1,%2};":"=l"(r):"f"(lo),"f"(hi));return r;}
__device__ __forceinline__ void upk(u64 v,float&lo,float&hi){asm("mov.b64 {%0,%1},%2;":"=f"(lo),"=f"(hi):"l"(v));}
__device__ __forceinline__ void fma2(u64&d,u64 a,u64 b){asm("fma.rn.f32x2 %0,%1,%2,%0;":"+l"(d):"l"(a),"l"(b));}
__device__ __forceinline__ float silu(float x){return __fdividef(x, 1.f + __expf(-x));}
__device__ __forceinline__ void red2(float*p,float a,float b){
    asm volatile("red.global.add.v2.f32 [%0],{%1,%2};"::"l"(p),"f"(a),"f"(b):"memory");}
__device__ __forceinline__ u32 prmt7632(u32 a,u32 b){u32 d;asm("prmt.b32 %0,%1,%2,0x7632;":"=r"(d):"r"(a),"r"(b));return d;}
__device__ __forceinline__ u32 cvt2(float hi,float lo){u32 d;asm("cvt.rn.bf16x2.f32 %0,%1,%2;":"=r"(d):"f"(hi),"f"(lo));return d;}
__device__ __forceinline__ float trunchi(float x){return __uint_as_float(__float_as_uint(x)&0xffff0000u);}
__device__ __forceinline__ int pmap(int j){return (j&~7)|((j&3)<<1)|((j>>2)&1);}
__device__ __forceinline__ void mmab(float* c,u32 a0,u32 a1,u32 a2,u32 a3,u32 b0,u32 b1){
    asm("mma.sync.aligned.m16n8k16.row.col.f32.bf16.bf16.f32 "
        "{%0,%1,%2,%3},{%4,%5,%6,%7},{%8,%9},{%0,%1,%2,%3};"
        :"+f"(c[0]),"+f"(c[1]),"+f"(c[2]),"+f"(c[3])
        :"r"(a0),"r"(a1),"r"(a2),"r"(a3),"r"(b0),"r"(b1));
}
/* pack float2 (k-consecutive pair) into hi/lo planes of buffer B at row r, phys idx p */
__device__ __forceinline__ void wrpack(u32* B,int r,int p,float2 o){
    B[r*34+p]       = prmt7632(__float_as_uint(o.x),__float_as_uint(o.y));
    B[r*34+p+PLANE] = cvt2(o.y-trunchi(o.y), o.x-trunchi(o.x));
}

/* bf16 split-P warp GEMM: D(16x32/warp) += X(128x64, hi/lo u32 planes) @ W.
   W fragment u32: hi at ((g*4+k16)*32+lane)*2+{0,1}; lo at +2048. */
template<int P>
__device__ __forceinline__ void mma_round(const u32* __restrict__ X,const u32* __restrict__ Whi,
                                          int lane,int m0,int gbase,float acc[4][4]){
    const int q=lane&3, r0=m0+(lane>>2), r1=r0+8;
    const u32* Xlo=X+PLANE;
    const u32* Wlo=Whi+2048;
#pragma unroll
    for(int k16=0;k16<4;++k16){
        int ax0=r0*34+k16*8+2*q, ax1=r1*34+k16*8+2*q;
        uint2 h0=*(const uint2*)(X+ax0), h1=*(const uint2*)(X+ax1);
        uint2 l0=make_uint2(0,0), l1=make_uint2(0,0);
        if(P>=2){ l0=*(const uint2*)(Xlo+ax0); l1=*(const uint2*)(Xlo+ax1); }
#pragma unroll
        for(int nt=0;nt<4;++nt){
            int wb=(((gbase+nt)*4+k16)*32+lane)*2;
            uint2 bh=*(const uint2*)(Whi+wb);
            mmab(acc[nt],h0.x,h1.x,h0.y,h1.y,bh.x,bh.y);
            if(P>=2) mmab(acc[nt],l0.x,l1.x,l0.y,l1.y,bh.x,bh.y);
            if(P>=3){ uint2 bl=*(const uint2*)(Wlo+wb);
                      mmab(acc[nt],h0.x,h1.x,h0.y,h1.y,bl.x,bl.y); }
        }
    }
}

/* ---- fp32 register GEMM for prep/nodes ---- */
template<int K>
__device__ __forceinline__ void gemm4(const float* __restrict__ X,const float* __restrict__ W,
                                      int ty,int c0,u64 acc[4][4]){
#pragma unroll 2
    for(int k4=0;k4<K/4;++k4){
        float4 xv[4];
#pragma unroll
        for(int i=0;i<4;++i) xv[i]=*(const float4*)(X+(ty*4+i)*STRIDE+k4*4);
#pragma unroll
        for(int kk=0;kk<4;++kk){
            const float* Wk=W+(k4*4+kk)*64;
            float4 wa=*(const float4*)(Wk+c0), wb=*(const float4*)(Wk+c0+32);
            u64 w0=pk(wa.x,wa.y),w1=pk(wa.z,wa.w),w2=pk(wb.x,wb.y),w3=pk(wb.z,wb.w);
#pragma unroll
            for(int i=0;i<4;++i){
                float x=(kk==0)?xv[i].x:(kk==1)?xv[i].y:(kk==2)?xv[i].z:xv[i].w;
                u64 xp=pk(x,x);
                fma2(acc[i][0],xp,w0);fma2(acc[i][1],xp,w1);
                fma2(acc[i][2],xp,w2);fma2(acc[i][3],xp,w3);
            }
        }
    }
}

/* =================== Kernel A: prep =================== */
#define A_W1A 0
#define A_W1B 4096
#define A_SH1 8192
#define A_SMEMF (8192+128*STRIDE)
__global__ void __launch_bounds__(256,1)
kernel_prep(const float* __restrict__ h,const float* __restrict__ node_embed,
            const float* __restrict__ mes_w1,const int* __restrict__ node_holder,
            const int* __restrict__ jt_idx){
    extern __shared__ float s[];
    const int tid=threadIdx.x, nb=blockIdx.x*128;
    for(int i=tid;i<4096;i+=256){s[A_W1A+i]=mes_w1[i];s[A_W1B+i]=mes_w1[4096+i];}
    for(int i=tid;i<128*64;i+=256){
        int l=i>>6,o=i&63,node=nb+l,cand=node/MAXA;
        int jn=node_holder[node],j=jt_idx[cand],jn1=jn>0?jn-1:0;
        float v=h[(size_t)node*64+o]+node_embed[((size_t)j*MMM+jn1)*64+o];
        s[A_SH1+l*STRIDE+o]=v; g_h1[(size_t)node*64+o]=v; g_agg[(size_t)node*64+o]=0.f;
    }
    __syncthreads();
    const int tx=tid&7, ty=tid>>3, c0=tx*4;
    u64 acc[4][4];
#pragma unroll
    for(int i=0;i<4;++i)
#pragma unroll
        for(int p=0;p<4;++p) acc[i][p]=0ull;
    gemm4<64>(s+A_SH1,s+A_W1A,ty,c0,acc);
#pragma unroll
    for(int i=0;i<4;++i){
        size_t b=(size_t)(nb+ty*4+i)*64; float v[8];
#pragma unroll
        for(int p=0;p<4;++p) upk(acc[i][p],v[2*p],v[2*p+1]);
        *(float4*)(g_P+b+c0)=make_float4(v[0],v[1],v[2],v[3]);
        *(float4*)(g_P+b+c0+32)=make_float4(v[4],v[5],v[6],v[7]);
    }
#pragma unroll
    for(int i=0;i<4;++i)
#pragma unroll
        for(int p=0;p<4;++p) acc[i][p]=0ull;
    gemm4<64>(s+A_SH1,s+A_W1B,ty,c0,acc);
#pragma unroll
    for(int i=0;i<4;++i){
        size_t b=(size_t)(nb+ty*4+i)*64; float v[8];
#pragma unroll
        for(int p=0;p<4;++p) upk(acc[i][p],v[2*p],v[2*p+1]);
        *(float4*)(g_Q+b+c0)=make_float4(v[0],v[1],v[2],v[3]);
        *(float4*)(g_Q+b+c0+32)=make_float4(v[4],v[5],v[6],v[7]);
    }
}

/* =================== Kernel B: edges (bf16x3 mma, planar) =================== */
#define WF      0
#define SB_B1   24576
#define SB_W1R  24640
#define SB_B2   24704
#define SB_CB1  24768
#define SB_CW2  24832
#define SB_EB1  24896
#define SB_EW1R 24960
#define SB_EB2  25024
#define BUFE    25088
#define BUFT    33792
#define BUFF    42496
#define SCOL    51200
#define SMB     51328
#define SEM     51456
#define SRAD    51584
#define SCD     51712
#define SGT     52096
#define STR     52352
#define B_SMEMF 52736
#define TBE     512

__global__ void __launch_bounds__(TBE,1)
kernel_edges(const float* __restrict__ coord,const float* __restrict__ edge_attr,
             const float* __restrict__ jt_mess,const float* __restrict__ node_mask,
             const float* __restrict__ edge_mask,
             const float* __restrict__ mes_w1,const float* __restrict__ mes_b1,
             const float* __restrict__ mes_w2,const float* __restrict__ mes_b2,
             const float* __restrict__ edge_w1,const float* __restrict__ edge_b1,
             const float* __restrict__ edge_w2,const float* __restrict__ edge_b2,
             const float* __restrict__ coord_w1,const float* __restrict__ coord_b1,
             const float* __restrict__ coord_w2,
             const int* __restrict__ colidx,const int* __restrict__ mess_holder,
             const int* __restrict__ jt_idx,
             float* __restrict__ outC,float* __restrict__ outE){
    extern __shared__ float s[];
    int* scol=(int*)(s+SCOL); int* smb=(int*)(s+SMB);
    u32* wfrag=(u32*)(s+WF);
    u32* BE=(u32*)(s+BUFE); u32* BT=(u32*)(s+BUFT); u32* BF=(u32*)(s+BUFF);
    const int tid=threadIdx.x, wid=tid>>5, lane=tid&31;
    const int mrow=wid>>1, nhalf=wid&1;
    const int m0=mrow*16, gbase=nhalf*4;
    const int q=lane&3;
    const int cb=nhalf*32+q*2;

    /* pack 6 weight matrices: hi at rest=((g*4+k16)*32+ln)*2+rg, lo at +2048 */
    for(int idx=tid;idx<6*4096;idx+=TBE){
        int m=idx>>12, t=idx&4095, hl=t>>11, rest=t&2047;
        int rg=rest&1, ln=(rest>>1)&31, k16=(rest>>6)&3, g=rest>>8;
        int n=g*8+(ln>>2), k0=k16*16+(ln&3)*2+rg*8;
        const float* src=(m==0)?mes_w1+129*64:(m==1)?mes_w2:(m==2)?coord_w1
                        :(m==3)?edge_w1:(m==4)?edge_w1+65*64:edge_w2;
        float w0=src[k0*64+n], w1=src[(k0+1)*64+n];
        u32 v;
        if(hl==0) v=prmt7632(__float_as_uint(w0),__float_as_uint(w1));
        else      v=cvt2(w1-trunchi(w1), w0-trunchi(w0));
        wfrag[m*4096+hl*2048+rest]=v;
    }
    if(tid<64){
        s[SB_B1+tid]=mes_b1[tid];   s[SB_W1R+tid]=mes_w1[128*64+tid];
        s[SB_B2+tid]=mes_b2[tid];   s[SB_CB1+tid]=coord_b1[tid];
        s[SB_CW2+tid]=coord_w2[tid];s[SB_EB1+tid]=edge_b1[tid];
        s[SB_EW1R+tid]=edge_w1[64*64+tid]; s[SB_EB2+tid]=edge_b2[tid];
    }
    __syncthreads();

    /* per-thread physical indices for the 4 nt column pairs */
    int pidx[4];
#pragma unroll
    for(int nt=0;nt<4;++nt) pidx[nt]=pmap(nhalf*16+nt*4+q);

    for(int tile=blockIdx.x;tile<NTILES;tile+=gridDim.x){
        const int e0=tile*TILE_E;

        if(tid<128){
            int ee=e0+tid, c=colidx[ee]; scol[tid]=c;
            int rr=ee>>4, cand=rr/MAXA, am=rr-cand*MAXA, ac=c-cand*MAXA;
            const int* jp=mess_holder+((((size_t)cand*MAXA+am)*MAXA+ac)<<1);
            int jr=jp[0],jc=jp[1],mb=-1;
            if(jr!=0&&jc!=0) mb=((jt_idx[cand]*MMM+(jr-1))*MMM+(jc-1))*64;
            smb[tid]=mb;
            s[SEM+tid]=edge_mask[ee];
            float dx=coord[rr*3+0]-coord[c*3+0];
            float dy=coord[rr*3+1]-coord[c*3+1];
            float dz=coord[rr*3+2]-coord[c*3+2];
            float rad=dx*dx+dy*dy+dz*dz; s[SRAD+tid]=rad;
            float inv=1.f/(sqrtf(rad+1e-8f)+1.f);
            s[SCD+tid*3+0]=dx*inv; s[SCD+tid*3+1]=dy*inv; s[SCD+tid*3+2]=dz*inv;
        }
        __syncthreads();

        const int r0=m0+(lane>>2), r1=r0+8;
        const int nrn=(e0+r0)>>4;
        const int col0=scol[r0], col1=scol[r1];

        float2 Pv[4],Q0v[4],Q1v[4];
#pragma unroll
        for(int nt=0;nt<4;++nt){
            Pv[nt] =*(const float2*)(g_P+(size_t)nrn *64+cb+nt*8);
            Q0v[nt]=*(const float2*)(g_Q+(size_t)col0*64+cb+nt*8);
            Q1v[nt]=*(const float2*)(g_Q+(size_t)col1*64+cb+nt*8);
        }

        /* stage bufE = edge_attr + mess, split into hi/lo planes */
        for(int idx=tid;idx<128*16;idx+=TBE){
            int e=idx>>4,o4=(idx&15)<<2;
            int eg=e0+e, mb=smb[e];
            float4 v=*(const float4*)(edge_attr+(size_t)eg*64+o4);
            if(mb>=0){ float4 m=*(const float4*)(jt_mess+(size_t)mb+o4);
                v.x+=m.x;v.y+=m.y;v.z+=m.z;v.w+=m.w; }
            int j0=o4>>1;
            wrpack(BE,e,pmap(j0),  make_float2(v.x,v.y));
            wrpack(BE,e,pmap(j0+1),make_float2(v.z,v.w));
        }
        __syncthreads();

        float acc[4][4];
        const float rad0=s[SRAD+r0], rad1=s[SRAD+r1];
        const float em0=s[SEM+r0],  em1=s[SEM+r1];

        /* GEMM1: bufE@W1E + P + Q + rad*w1r + b1 ; silu -> bufT */
#pragma unroll
        for(int nt=0;nt<4;++nt){acc[nt][0]=acc[nt][1]=acc[nt][2]=acc[nt][3]=0.f;}
        mma_round<3>(BE,wfrag+0*4096,lane,m0,gbase,acc);
#pragma unroll
        for(int nt=0;nt<4;++nt){
            int c=cb+nt*8;
            float2 bv=*(float2*)(s+SB_B1+c), wv=*(float2*)(s+SB_W1R+c);
            float2 o0,o1;
            o0.x=silu(acc[nt][0]+bv.x+rad0*wv.x+Pv[nt].x+Q0v[nt].x);
            o0.y=silu(acc[nt][1]+bv.y+rad0*wv.y+Pv[nt].y+Q0v[nt].y);
            o1.x=silu(acc[nt][2]+bv.x+rad1*wv.x+Pv[nt].x+Q1v[nt].x);
            o1.y=silu(acc[nt][3]+bv.y+rad1*wv.y+Pv[nt].y+Q1v[nt].y);
            wrpack(BT,r0,pidx[nt],o0);
            wrpack(BT,r1,pidx[nt],o1);
        }
        __syncthreads();

        /* GEMM2: bufT@W2 ; silu(+b2)*em -> bufF + agg red */
#pragma unroll
        for(int nt=0;nt<4;++nt){acc[nt][0]=acc[nt][1]=acc[nt][2]=acc[nt][3]=0.f;}
        mma_round<3>(BT,wfrag+1*4096,lane,m0,gbase,acc);
#pragma unroll
        for(int nt=0;nt<4;++nt){
            int c=cb+nt*8;
            float2 bv=*(float2*)(s+SB_B2+c);
            float v0=silu(acc[nt][0]+bv.x)*em0, v1=silu(acc[nt][1]+bv.y)*em0;
            float v2=silu(acc[nt][2]+bv.x)*em1, v3=silu(acc[nt][3]+bv.y)*em1;
            wrpack(BF,r0,pidx[nt],make_float2(v0,v1));
            wrpack(BF,r1,pidx[nt],make_float2(v2,v3));
            red2(g_agg+(size_t)col0*64+c,v0,v1);
            red2(g_agg+(size_t)col1*64+c,v2,v3);
        }
        __syncthreads();

        /* GEMM3: coord gate (1-pass) */
#pragma unroll
        for(int nt=0;nt<4;++nt){acc[nt][0]=acc[nt][1]=acc[nt][2]=acc[nt][3]=0.f;}
        mma_round<1>(BF,wfrag+2*4096,lane,m0,gbase,acc);
        {
            float pd0=0.f,pd1=0.f;
#pragma unroll
            for(int nt=0;nt<4;++nt){
                int c=cb+nt*8;
                float2 bv=*(float2*)(s+SB_CB1+c), cw=*(float2*)(s+SB_CW2+c);
                pd0+=silu(acc[nt][0]+bv.x)*cw.x+silu(acc[nt][1]+bv.y)*cw.y;
                pd1+=silu(acc[nt][2]+bv.x)*cw.x+silu(acc[nt][3]+bv.y)*cw.y;
            }
            pd0+=__shfl_xor_sync(0xffffffffu,pd0,1); pd0+=__shfl_xor_sync(0xffffffffu,pd0,2);
            pd1+=__shfl_xor_sync(0xffffffffu,pd1,1); pd1+=__shfl_xor_sync(0xffffffffu,pd1,2);
            if(q==0){ s[SGT+nhalf*128+r0]=pd0; s[SGT+nhalf*128+r1]=pd1; }
        }
        __syncthreads();

        /* STR scatter overlapped with GEMM4 MMAs (disjoint smem regions) */
        if(tid<128){
            float g=(s[SGT+tid]+s[SGT+128+tid])*s[SEM+tid];
            s[STR+tid*3+0]=s[SCD+tid*3+0]*g;
            s[STR+tid*3+1]=s[SCD+tid*3+1]*g;
            s[STR+tid*3+2]=s[SCD+tid*3+2]*g;
        }
        /* GEMM4: bufF@EW1A + bufE@EW1B */
#pragma unroll
        for(int nt=0;nt<4;++nt){acc[nt][0]=acc[nt][1]=acc[nt][2]=acc[nt][3]=0.f;}
        mma_round<3>(BF,wfrag+3*4096,lane,m0,gbase,acc);
        mma_round<3>(BE,wfrag+4*4096,lane,m0,gbase,acc);
        __syncthreads();
        if(tid<NPT*3){
            int n=tid/3,c=tid-n*3; float sum=0.f;
#pragma unroll
            for(int k=0;k<DEG;++k) sum+=s[STR+(n*DEG+k)*3+c];
            int gn=tile*NPT+n;
            outC[gn*3+c]=(coord[gn*3+c]+sum)*node_mask[gn];
        }
        /* GEMM4 epilogue: silu(+eb1+rad*ew1r) -> bufT */
#pragma unroll
        for(int nt=0;nt<4;++nt){
            int c=cb+nt*8;
            float2 bv=*(float2*)(s+SB_EB1+c), wv=*(float2*)(s+SB_EW1R+c);
            float2 o0,o1;
            o0.x=silu(acc[nt][0]+bv.x+rad0*wv.x); o0.y=silu(acc[nt][1]+bv.y+rad0*wv.y);
            o1.x=silu(acc[nt][2]+bv.x+rad1*wv.x); o1.y=silu(acc[nt][3]+bv.y+rad1*wv.y);
            wrpack(BT,r0,pidx[nt],o0);
            wrpack(BT,r1,pidx[nt],o1);
        }
        __syncthreads();

        /* GEMM5: bufT@EW2 ; (+eb2)*em -> outE */
#pragma unroll
        for(int nt=0;nt<4;++nt){acc[nt][0]=acc[nt][1]=acc[nt][2]=acc[nt][3]=0.f;}
        mma_round<3>(BT,wfrag+5*4096,lane,m0,gbase,acc);
#pragma unroll
        for(int nt=0;nt<4;++nt){
            int c=cb+nt*8;
            float2 bv=*(float2*)(s+SB_EB2+c);
            *(float2*)(outE+(size_t)(e0+r0)*64+c)=
                make_float2((acc[nt][0]+bv.x)*em0,(acc[nt][1]+bv.y)*em0);
            *(float2*)(outE+(size_t)(e0+r1)*64+c)=
                make_float2((acc[nt][2]+bv.x)*em1,(acc[nt][3]+bv.y)*em1);
        }
        __syncthreads();
    }
}

/* =================== Kernel C: node MLP =================== */
#define C_NW1 0
#define C_NW2 8192
#define C_NB1 12288
#define C_NB2 12352
#define C_BA  12416
#define C_BB  (12416+128*STRIDE)
#define C_BT  (12416+2*128*STRIDE)
#define C_SMEMF (12416+3*128*STRIDE)
__global__ void __launch_bounds__(256,1)
kernel_nodes(const float* __restrict__ node_w1,const float* __restrict__ node_b1,
             const float* __restrict__ node_w2,const float* __restrict__ node_b2,
             const float* __restrict__ node_mask,float* __restrict__ outH){
    extern __shared__ float s[];
    const int tid=threadIdx.x, nb=blockIdx.x*128;
    const int tx=tid&7, ty=tid>>3, c0=tx*4;
    for(int i=tid;i<8192;i+=256) s[C_NW1+i]=node_w1[i];
    for(int i=tid;i<4096;i+=256) s[C_NW2+i]=node_w2[i];
    if(tid<64){s[C_NB1+tid]=node_b1[tid];s[C_NB2+tid]=node_b2[tid];}
    for(int i=tid;i<128*16;i+=256){
        int l=i>>4,o4=(i&15)<<2; size_t b=(size_t)(nb+l)*64+o4;
        *(float4*)(s+C_BA+l*STRIDE+o4)=*(const float4*)(g_h1+b);
        *(float4*)(s+C_BB+l*STRIDE+o4)=*(const float4*)(g_agg+b);
    }
    __syncthreads();
    u64 acc[4][4];
#pragma unroll
    for(int i=0;i<4;++i){
        acc[i][0]=pk(s[C_NB1+c0],s[C_NB1+c0+1]);acc[i][1]=pk(s[C_NB1+c0+2],s[C_NB1+c0+3]);
        acc[i][2]=pk(s[C_NB1+c0+32],s[C_NB1+c0+33]);acc[i][3]=pk(s[C_NB1+c0+34],s[C_NB1+c0+35]);
    }
    gemm4<64>(s+C_BA,s+C_NW1,ty,c0,acc);
    gemm4<64>(s+C_BB,s+C_NW1+64*64,ty,c0,acc);
#pragma unroll
    for(int i=0;i<4;++i){
        float* d=s+C_BT+(ty*4+i)*STRIDE; float a,b;
        upk(acc[i][0],a,b);d[c0+0]=silu(a);d[c0+1]=silu(b);
        upk(acc[i][1],a,b);d[c0+2]=silu(a);d[c0+3]=silu(b);
        upk(acc[i][2],a,b);d[c0+32]=silu(a);d[c0+33]=silu(b);
        upk(acc[i][3],a,b);d[c0+34]=silu(a);d[c0+35]=silu(b);
    }
    __syncthreads();
#pragma unroll
    for(int i=0;i<4;++i){
        acc[i][0]=pk(s[C_NB2+c0],s[C_NB2+c0+1]);acc[i][1]=pk(s[C_NB2+c0+2],s[C_NB2+c0+3]);
        acc[i][2]=pk(s[C_NB2+c0+32],s[C_NB2+c0+33]);acc[i][3]=pk(s[C_NB2+c0+34],s[C_NB2+c0+35]);
    }
    gemm4<64>(s+C_BT,s+C_NW2,ty,c0,acc);
#pragma unroll
    for(int i=0;i<4;++i){
        int l=ty*4+i,node=nb+l; float nm=node_mask[node];
        const float* h1p=s+C_BA+l*STRIDE; float a,b,v0,v1,v2,v3;
        size_t base=(size_t)node*64;
        upk(acc[i][0],a,b);v0=(h1p[c0+0]+a)*nm;v1=(h1p[c0+1]+b)*nm;
        upk(acc[i][1],a,b);v2=(h1p[c0+2]+a)*nm;v3=(h1p[c0+3]+b)*nm;
        *(float4*)(outH+base+c0)=make_float4(v0,v1,v2,v3);
        upk(acc[i][2],a,b);v0=(h1p[c0+32]+a)*nm;v1=(h1p[c0+33]+b)*nm;
        upk(acc[i][3],a,b);v2=(h1p[c0+34]+a)*nm;v3=(h1p[c0+35]+b)*nm;
        *(float4*)(outH+base+c0+32)=make_float4(v0,v1,v2,v3);
    }
}

/* =================== launcher =================== */
extern "C" void kernel_launch(void* const* d_in, const int* in_sizes, int n_in,
                              void* d_out, int out_size)
{
    const float* h          =(const float*)d_in[0];
    const float* coord      =(const float*)d_in[1];
    const float* edge_attr  =(const float*)d_in[2];
    const float* jt_mess    =(const float*)d_in[3];
    const float* node_embed =(const float*)d_in[4];
    const float* node_mask  =(const float*)d_in[5];
    const float* edge_mask  =(const float*)d_in[6];
    const float* mes_w1     =(const float*)d_in[7];
    const float* mes_b1     =(const float*)d_in[8];
    const float* mes_w2     =(const float*)d_in[9];
    const float* mes_b2     =(const float*)d_in[10];
    const float* edge_w1    =(const float*)d_in[11];
    const float* edge_b1    =(const float*)d_in[12];
    const float* edge_w2    =(const float*)d_in[13];
    const float* edge_b2    =(const float*)d_in[14];
    const float* node_w1    =(const float*)d_in[15];
    const float* node_b1    =(const float*)d_in[16];
    const float* node_w2    =(const float*)d_in[17];
    const float* node_b2    =(const float*)d_in[18];
    const float* coord_w1   =(const float*)d_in[19];
    const float* coord_b1   =(const float*)d_in[20];
    const float* coord_w2   =(const float*)d_in[21];
    const int*   edge_index =(const int*)d_in[22];
    const int*   mess_holder=(const int*)d_in[23];
    const int*   node_holder=(const int*)d_in[24];
    const int*   jt_idx     =(const int*)d_in[25];

    float* outH=(float*)d_out;
    float* outC=outH+(size_t)NN*64;
    float* outE=outC+(size_t)NN*3;

    const int smemA=A_SMEMF*4, smemB=B_SMEMF*4, smemC=C_SMEMF*4;
    cudaFuncSetAttribute(kernel_prep, cudaFuncAttributeMaxDynamicSharedMemorySize,smemA);
    cudaFuncSetAttribute(kernel_edges,cudaFuncAttributeMaxDynamicSharedMemorySize,smemB);
    cudaFuncSetAttribute(kernel_nodes,cudaFuncAttributeMaxDynamicSharedMemorySize,smemC);

    kernel_prep<<<NN/128,256,smemA>>>(h,node_embed,mes_w1,node_holder,jt_idx);
    kernel_edges<<<148,TBE,smemB>>>(coord,edge_attr,jt_mess,node_mask,edge_mask,
                                    mes_w1,mes_b1,mes_w2,mes_b2,
                                    edge_w1,edge_b1,edge_w2,edge_b2,
                                    coord_w1,coord_b1,coord_w2,
                                    edge_index+NE,mess_holder,jt_idx,outC,outE);
    kernel_nodes<<<NN/128,256,smemC>>>(node_w1,node_b1,node_w2,node_b2,node_mask,outH);
}

// round 17
// speedup vs baseline: 2.1460x; 1.2127x over previous
#include <cuda_runtime.h>
#include <cuda_bf16.h>
#include <math.h>
#include <stdint.h>

#define MAXA 54
#define NN   (1024*MAXA)
#define DEG  16
#define NE   (NN*DEG)
#define MMM  16
#define TILE_E 128
#define NTILES (NE/TILE_E)
#define NPT  (TILE_E/DEG)
#define STRIDE 68
#define PLANE 4352            /* 128*34 u32 per plane */

typedef unsigned long long u64;
typedef unsigned int u32;

__device__ float g_h1 [(size_t)NN*64];
__device__ float g_P  [(size_t)NN*64];
__device__ float g_Q  [(size_t)NN*64];
__device__ float g_agg[(size_t)NN*64];

__device__ __forceinline__ u64 pk(float lo, float hi){u64 r;asm("mov.b64 %0,{%1,%2};":"=l"(r):"f"(lo),"f"(hi));return r;}
__device__ __forceinline__ void upk(u64 v,float&lo,float&hi){asm("mov.b64 {%0,%1},%2;":"=f"(lo),"=f"(hi):"l"(v));}
__device__ __forceinline__ void fma2(u64&d,u64 a,u64 b){asm("fma.rn.f32x2 %0,%1,%2,%0;":"+l"(d):"l"(a),"l"(b));}
__device__ __forceinline__ float silu(float x){return __fdividef(x, 1.f + __expf(-x));}
__device__ __forceinline__ void red2(float*p,float a,float b){
    asm volatile("red.global.add.v2.f32 [%0],{%1,%2};"::"l"(p),"f"(a),"f"(b):"memory");}
__device__ __forceinline__ u32 prmt7632(u32 a,u32 b){u32 d;asm("prmt.b32 %0,%1,%2,0x7632;":"=r"(d):"r"(a),"r"(b));return d;}
__device__ __forceinline__ u32 cvt2(float hi,float lo){u32 d;asm("cvt.rn.bf16x2.f32 %0,%1,%2;":"=r"(d):"f"(hi),"f"(lo));return d;}
__device__ __forceinline__ float trunchi(float x){return __uint_as_float(__float_as_uint(x)&0xffff0000u);}
__device__ __forceinline__ int pmap(int j){return (j&~7)|((j&3)<<1)|((j>>2)&1);}
__device__ __forceinline__ void mmab(float* c,u32 a0,u32 a1,u32 a2,u32 a3,u32 b0,u32 b1){
    asm("mma.sync.aligned.m16n8k16.row.col.f32.bf16.bf16.f32 "
        "{%0,%1,%2,%3},{%4,%5,%6,%7},{%8,%9},{%0,%1,%2,%3};"
        :"+f"(c[0]),"+f"(c[1]),"+f"(c[2]),"+f"(c[3])
        :"r"(a0),"r"(a1),"r"(a2),"r"(a3),"r"(b0),"r"(b1));
}
__device__ __forceinline__ void wrpack(u32* B,int r,int p,float2 o){
    B[r*34+p]       = prmt7632(__float_as_uint(o.x),__float_as_uint(o.y));
    B[r*34+p+PLANE] = cvt2(o.y-trunchi(o.y), o.x-trunchi(o.x));
}

/* bf16 split-P warp GEMM: D(16x32/warp) += X(rows m0..m0+15, hi/lo planes) @ W. */
template<int P>
__device__ __forceinline__ void mma_round(const u32* __restrict__ X,const u32* __restrict__ Whi,
                                          int lane,int m0,int gbase,float acc[4][4]){
    const int q=lane&3, r0=m0+(lane>>2), r1=r0+8;
    const u32* Xlo=X+PLANE;
    const u32* Wlo=Whi+2048;
#pragma unroll
    for(int k16=0;k16<4;++k16){
        int ax0=r0*34+k16*8+2*q, ax1=r1*34+k16*8+2*q;
        uint2 h0=*(const uint2*)(X+ax0), h1=*(const uint2*)(X+ax1);
        uint2 l0=make_uint2(0,0), l1=make_uint2(0,0);
        if(P>=2){ l0=*(const uint2*)(Xlo+ax0); l1=*(const uint2*)(Xlo+ax1); }
#pragma unroll
        for(int nt=0;nt<4;++nt){
            int wb=(((gbase+nt)*4+k16)*32+lane)*2;
            uint2 bh=*(const uint2*)(Whi+wb);
            mmab(acc[nt],h0.x,h1.x,h0.y,h1.y,bh.x,bh.y);
            if(P>=2) mmab(acc[nt],l0.x,l1.x,l0.y,l1.y,bh.x,bh.y);
            if(P>=3){ uint2 bl=*(const uint2*)(Wlo+wb);
                      mmab(acc[nt],h0.x,h1.x,h0.y,h1.y,bl.x,bl.y); }
        }
    }
}

/* ---- fp32 register GEMM for prep/nodes ---- */
template<int K>
__device__ __forceinline__ void gemm4(const float* __restrict__ X,const float* __restrict__ W,
                                      int ty,int c0,u64 acc[4][4]){
#pragma unroll 2
    for(int k4=0;k4<K/4;++k4){
        float4 xv[4];
#pragma unroll
        for(int i=0;i<4;++i) xv[i]=*(const float4*)(X+(ty*4+i)*STRIDE+k4*4);
#pragma unroll
        for(int kk=0;kk<4;++kk){
            const float* Wk=W+(k4*4+kk)*64;
            float4 wa=*(const float4*)(Wk+c0), wb=*(const float4*)(Wk+c0+32);
            u64 w0=pk(wa.x,wa.y),w1=pk(wa.z,wa.w),w2=pk(wb.x,wb.y),w3=pk(wb.z,wb.w);
#pragma unroll
            for(int i=0;i<4;++i){
                float x=(kk==0)?xv[i].x:(kk==1)?xv[i].y:(kk==2)?xv[i].z:xv[i].w;
                u64 xp=pk(x,x);
                fma2(acc[i][0],xp,w0);fma2(acc[i][1],xp,w1);
                fma2(acc[i][2],xp,w2);fma2(acc[i][3],xp,w3);
            }
        }
    }
}

/* =================== Kernel A: prep =================== */
#define A_W1A 0
#define A_W1B 4096
#define A_SH1 8192
#define A_SMEMF (8192+128*STRIDE)
__global__ void __launch_bounds__(256,1)
kernel_prep(const float* __restrict__ h,const float* __restrict__ node_embed,
            const float* __restrict__ mes_w1,const int* __restrict__ node_holder,
            const int* __restrict__ jt_idx){
    extern __shared__ float s[];
    const int tid=threadIdx.x, nb=blockIdx.x*128;
    for(int i=tid;i<4096;i+=256){s[A_W1A+i]=mes_w1[i];s[A_W1B+i]=mes_w1[4096+i];}
    for(int i=tid;i<128*64;i+=256){
        int l=i>>6,o=i&63,node=nb+l,cand=node/MAXA;
        int jn=node_holder[node],j=jt_idx[cand],jn1=jn>0?jn-1:0;
        float v=h[(size_t)node*64+o]+node_embed[((size_t)j*MMM+jn1)*64+o];
        s[A_SH1+l*STRIDE+o]=v; g_h1[(size_t)node*64+o]=v; g_agg[(size_t)node*64+o]=0.f;
    }
    __syncthreads();
    const int tx=tid&7, ty=tid>>3, c0=tx*4;
    u64 acc[4][4];
#pragma unroll
    for(int i=0;i<4;++i)
#pragma unroll
        for(int p=0;p<4;++p) acc[i][p]=0ull;
    gemm4<64>(s+A_SH1,s+A_W1A,ty,c0,acc);
#pragma unroll
    for(int i=0;i<4;++i){
        size_t b=(size_t)(nb+ty*4+i)*64; float v[8];
#pragma unroll
        for(int p=0;p<4;++p) upk(acc[i][p],v[2*p],v[2*p+1]);
        *(float4*)(g_P+b+c0)=make_float4(v[0],v[1],v[2],v[3]);
        *(float4*)(g_P+b+c0+32)=make_float4(v[4],v[5],v[6],v[7]);
    }
#pragma unroll
    for(int i=0;i<4;++i)
#pragma unroll
        for(int p=0;p<4;++p) acc[i][p]=0ull;
    gemm4<64>(s+A_SH1,s+A_W1B,ty,c0,acc);
#pragma unroll
    for(int i=0;i<4;++i){
        size_t b=(size_t)(nb+ty*4+i)*64; float v[8];
#pragma unroll
        for(int p=0;p<4;++p) upk(acc[i][p],v[2*p],v[2*p+1]);
        *(float4*)(g_Q+b+c0)=make_float4(v[0],v[1],v[2],v[3]);
        *(float4*)(g_Q+b+c0+32)=make_float4(v[4],v[5],v[6],v[7]);
    }
}

/* =================== Kernel B: edges (bf16x3 mma, pair pipelines) =========== */
#define WF      0
#define SB_B1   24576
#define SB_W1R  24640
#define SB_B2   24704
#define SB_CB1  24768
#define SB_CW2  24832
#define SB_EB1  24896
#define SB_EW1R 24960
#define SB_EB2  25024
#define BUFE    25088
#define BUFT    33792
#define BUFF    42496
#define SCOL    51200
#define SMB     51328
#define SEM     51456
#define SRAD    51584
#define SCD     51712
#define SGT     52096
#define STR     52352
#define B_SMEMF 52736
#define TBE     512
/* pair-local named barrier: 2 warps, 64 threads; ids 1..8 */
#define PBAR()  asm volatile("bar.sync %0, 64;"::"r"(mrow+1):"memory")

__global__ void __launch_bounds__(TBE,1)
kernel_edges(const float* __restrict__ coord,const float* __restrict__ edge_attr,
             const float* __restrict__ jt_mess,const float* __restrict__ node_mask,
             const float* __restrict__ edge_mask,
             const float* __restrict__ mes_w1,const float* __restrict__ mes_b1,
             const float* __restrict__ mes_w2,const float* __restrict__ mes_b2,
             const float* __restrict__ edge_w1,const float* __restrict__ edge_b1,
             const float* __restrict__ edge_w2,const float* __restrict__ edge_b2,
             const float* __restrict__ coord_w1,const float* __restrict__ coord_b1,
             const float* __restrict__ coord_w2,
             const int* __restrict__ colidx,const int* __restrict__ mess_holder,
             const int* __restrict__ jt_idx,
             float* __restrict__ outC,float* __restrict__ outE){
    extern __shared__ float s[];
    int* scol=(int*)(s+SCOL); int* smb=(int*)(s+SMB);
    u32* wfrag=(u32*)(s+WF);
    u32* BE=(u32*)(s+BUFE); u32* BT=(u32*)(s+BUFT); u32* BF=(u32*)(s+BUFF);
    const int tid=threadIdx.x, wid=tid>>5, lane=tid&31;
    const int mrow=wid>>1, nhalf=wid&1;
    const int m0=mrow*16, gbase=nhalf*4;
    const int q=lane&3;
    const int cb=nhalf*32+q*2;
    const int ptid=tid&63;            /* thread id within the 2-warp pair */

    /* pack 6 weight matrices (block-wide, once) */
    for(int idx=tid;idx<6*4096;idx+=TBE){
        int m=idx>>12, t=idx&4095, hl=t>>11, rest=t&2047;
        int rg=rest&1, ln=(rest>>1)&31, k16=(rest>>6)&3, g=rest>>8;
        int n=g*8+(ln>>2), k0=k16*16+(ln&3)*2+rg*8;
        const float* src=(m==0)?mes_w1+129*64:(m==1)?mes_w2:(m==2)?coord_w1
                        :(m==3)?edge_w1:(m==4)?edge_w1+65*64:edge_w2;
        float w0=src[k0*64+n], w1=src[(k0+1)*64+n];
        u32 v;
        if(hl==0) v=prmt7632(__float_as_uint(w0),__float_as_uint(w1));
        else      v=cvt2(w1-trunchi(w1), w0-trunchi(w0));
        wfrag[m*4096+hl*2048+rest]=v;
    }
    if(tid<64){
        s[SB_B1+tid]=mes_b1[tid];   s[SB_W1R+tid]=mes_w1[128*64+tid];
        s[SB_B2+tid]=mes_b2[tid];   s[SB_CB1+tid]=coord_b1[tid];
        s[SB_CW2+tid]=coord_w2[tid];s[SB_EB1+tid]=edge_b1[tid];
        s[SB_EW1R+tid]=edge_w1[64*64+tid]; s[SB_EB2+tid]=edge_b2[tid];
    }
    __syncthreads();

    int pidx[4];
#pragma unroll
    for(int nt=0;nt<4;++nt) pidx[nt]=pmap(nhalf*16+nt*4+q);

    /* each pair runs its own independent pipeline over all tiles */
    for(int tile=blockIdx.x;tile<NTILES;tile+=gridDim.x){
        const int e0=tile*TILE_E;

        /* ---- pair metadata: this pair's 16 edges ---- */
        if(ptid<16){
            int e=m0+ptid, ee=e0+e, c=colidx[ee]; scol[e]=c;
            int rr=ee>>4, cand=rr/MAXA, am=rr-cand*MAXA, ac=c-cand*MAXA;
            const int* jp=mess_holder+((((size_t)cand*MAXA+am)*MAXA+ac)<<1);
            int jr=jp[0],jc=jp[1],mb=-1;
            if(jr!=0&&jc!=0) mb=((jt_idx[cand]*MMM+(jr-1))*MMM+(jc-1))*64;
            smb[e]=mb;
            s[SEM+e]=edge_mask[ee];
            float dx=coord[rr*3+0]-coord[c*3+0];
            float dy=coord[rr*3+1]-coord[c*3+1];
            float dz=coord[rr*3+2]-coord[c*3+2];
            float rad=dx*dx+dy*dy+dz*dz; s[SRAD+e]=rad;
            float inv=1.f/(sqrtf(rad+1e-8f)+1.f);
            s[SCD+e*3+0]=dx*inv; s[SCD+e*3+1]=dy*inv; s[SCD+e*3+2]=dz*inv;
        }
        PBAR();

        const int r0=m0+(lane>>2), r1=r0+8;
        const int nrn=(e0+r0)>>4;
        const int col0=scol[r0], col1=scol[r1];

        float2 Pv[4],Q0v[4],Q1v[4];
#pragma unroll
        for(int nt=0;nt<4;++nt){
            Pv[nt] =*(const float2*)(g_P+(size_t)nrn *64+cb+nt*8);
            Q0v[nt]=*(const float2*)(g_Q+(size_t)col0*64+cb+nt*8);
            Q1v[nt]=*(const float2*)(g_Q+(size_t)col1*64+cb+nt*8);
        }

        /* ---- stage pair's 16 rows of bufE ---- */
        for(int idx=ptid;idx<16*16;idx+=64){
            int e=m0+(idx>>4), o4=(idx&15)<<2;
            int eg=e0+e, mb=smb[e];
            float4 v=*(const float4*)(edge_attr+(size_t)eg*64+o4);
            if(mb>=0){ float4 m=*(const float4*)(jt_mess+(size_t)mb+o4);
                v.x+=m.x;v.y+=m.y;v.z+=m.z;v.w+=m.w; }
            int j0=o4>>1;
            wrpack(BE,e,pmap(j0),  make_float2(v.x,v.y));
            wrpack(BE,e,pmap(j0+1),make_float2(v.z,v.w));
        }
        PBAR();

        float acc[4][4];
        const float rad0=s[SRAD+r0], rad1=s[SRAD+r1];
        const float em0=s[SEM+r0],  em1=s[SEM+r1];

        /* GEMM1: bufE@W1E + P + Q + rad*w1r + b1 ; silu -> bufT */
#pragma unroll
        for(int nt=0;nt<4;++nt){acc[nt][0]=acc[nt][1]=acc[nt][2]=acc[nt][3]=0.f;}
        mma_round<3>(BE,wfrag+0*4096,lane,m0,gbase,acc);
#pragma unroll
        for(int nt=0;nt<4;++nt){
            int c=cb+nt*8;
            float2 bv=*(float2*)(s+SB_B1+c), wv=*(float2*)(s+SB_W1R+c);
            float2 o0,o1;
            o0.x=silu(acc[nt][0]+bv.x+rad0*wv.x+Pv[nt].x+Q0v[nt].x);
            o0.y=silu(acc[nt][1]+bv.y+rad0*wv.y+Pv[nt].y+Q0v[nt].y);
            o1.x=silu(acc[nt][2]+bv.x+rad1*wv.x+Pv[nt].x+Q1v[nt].x);
            o1.y=silu(acc[nt][3]+bv.y+rad1*wv.y+Pv[nt].y+Q1v[nt].y);
            wrpack(BT,r0,pidx[nt],o0);
            wrpack(BT,r1,pidx[nt],o1);
        }
        PBAR();

        /* GEMM2: bufT@W2 ; silu(+b2)*em -> bufF + agg red */
#pragma unroll
        for(int nt=0;nt<4;++nt){acc[nt][0]=acc[nt][1]=acc[nt][2]=acc[nt][3]=0.f;}
        mma_round<3>(BT,wfrag+1*4096,lane,m0,gbase,acc);
#pragma unroll
        for(int nt=0;nt<4;++nt){
            int c=cb+nt*8;
            float2 bv=*(float2*)(s+SB_B2+c);
            float v0=silu(acc[nt][0]+bv.x)*em0, v1=silu(acc[nt][1]+bv.y)*em0;
            float v2=silu(acc[nt][2]+bv.x)*em1, v3=silu(acc[nt][3]+bv.y)*em1;
            wrpack(BF,r0,pidx[nt],make_float2(v0,v1));
            wrpack(BF,r1,pidx[nt],make_float2(v2,v3));
            red2(g_agg+(size_t)col0*64+c,v0,v1);
            red2(g_agg+(size_t)col1*64+c,v2,v3);
        }
        PBAR();

        /* GEMM3: coord gate (1-pass) */
#pragma unroll
        for(int nt=0;nt<4;++nt){acc[nt][0]=acc[nt][1]=acc[nt][2]=acc[nt][3]=0.f;}
        mma_round<1>(BF,wfrag+2*4096,lane,m0,gbase,acc);
        {
            float pd0=0.f,pd1=0.f;
#pragma unroll
            for(int nt=0;nt<4;++nt){
                int c=cb+nt*8;
                float2 bv=*(float2*)(s+SB_CB1+c), cw=*(float2*)(s+SB_CW2+c);
                pd0+=silu(acc[nt][0]+bv.x)*cw.x+silu(acc[nt][1]+bv.y)*cw.y;
                pd1+=silu(acc[nt][2]+bv.x)*cw.x+silu(acc[nt][3]+bv.y)*cw.y;
            }
            pd0+=__shfl_xor_sync(0xffffffffu,pd0,1); pd0+=__shfl_xor_sync(0xffffffffu,pd0,2);
            pd1+=__shfl_xor_sync(0xffffffffu,pd1,1); pd1+=__shfl_xor_sync(0xffffffffu,pd1,2);
            if(q==0){ s[SGT+nhalf*128+r0]=pd0; s[SGT+nhalf*128+r1]=pd1; }
        }
        PBAR();

        /* gate combine + STR for pair's 16 edges */
        if(ptid<16){
            int e=m0+ptid;
            float g=(s[SGT+e]+s[SGT+128+e])*s[SEM+e];
            s[STR+e*3+0]=s[SCD+e*3+0]*g;
            s[STR+e*3+1]=s[SCD+e*3+1]*g;
            s[STR+e*3+2]=s[SCD+e*3+2]*g;
        }
        /* GEMM4 MMAs overlap the STR scatter (disjoint smem) */
#pragma unroll
        for(int nt=0;nt<4;++nt){acc[nt][0]=acc[nt][1]=acc[nt][2]=acc[nt][3]=0.f;}
        mma_round<3>(BF,wfrag+3*4096,lane,m0,gbase,acc);
        mma_round<3>(BE,wfrag+4*4096,lane,m0,gbase,acc);
        PBAR();
        /* coord output: this pair's node = tile*NPT + mrow */
        if(ptid<3){
            int c=ptid; float sum=0.f;
#pragma unroll
            for(int k=0;k<DEG;++k) sum+=s[STR+(m0+k)*3+c];
            int gn=tile*NPT+mrow;
            outC[gn*3+c]=(coord[gn*3+c]+sum)*node_mask[gn];
        }
        /* GEMM4 epilogue: silu(+eb1+rad*ew1r) -> bufT */
#pragma unroll
        for(int nt=0;nt<4;++nt){
            int c=cb+nt*8;
            float2 bv=*(float2*)(s+SB_EB1+c), wv=*(float2*)(s+SB_EW1R+c);
            float2 o0,o1;
            o0.x=silu(acc[nt][0]+bv.x+rad0*wv.x); o0.y=silu(acc[nt][1]+bv.y+rad0*wv.y);
            o1.x=silu(acc[nt][2]+bv.x+rad1*wv.x); o1.y=silu(acc[nt][3]+bv.y+rad1*wv.y);
            wrpack(BT,r0,pidx[nt],o0);
            wrpack(BT,r1,pidx[nt],o1);
        }
        PBAR();

        /* GEMM5: bufT@EW2 ; (+eb2)*em -> outE */
#pragma unroll
        for(int nt=0;nt<4;++nt){acc[nt][0]=acc[nt][1]=acc[nt][2]=acc[nt][3]=0.f;}
        mma_round<3>(BT,wfrag+5*4096,lane,m0,gbase,acc);
#pragma unroll
        for(int nt=0;nt<4;++nt){
            int c=cb+nt*8;
            float2 bv=*(float2*)(s+SB_EB2+c);
            *(float2*)(outE+(size_t)(e0+r0)*64+c)=
                make_float2((acc[nt][0]+bv.x)*em0,(acc[nt][1]+bv.y)*em0);
            *(float2*)(outE+(size_t)(e0+r1)*64+c)=
                make_float2((acc[nt][2]+bv.x)*em1,(acc[nt][3]+bv.y)*em1);
        }
        PBAR();   /* pair's buffers reused next tile */
    }
}

/* =================== Kernel C: node MLP =================== */
#define C_NW1 0
#define C_NW2 8192
#define C_NB1 12288
#define C_NB2 12352
#define C_BA  12416
#define C_BB  (12416+128*STRIDE)
#define C_BT  (12416+2*128*STRIDE)
#define C_SMEMF (12416+3*128*STRIDE)
__global__ void __launch_bounds__(256,1)
kernel_nodes(const float* __restrict__ node_w1,const float* __restrict__ node_b1,
             const float* __restrict__ node_w2,const float* __restrict__ node_b2,
             const float* __restrict__ node_mask,float* __restrict__ outH){
    extern __shared__ float s[];
    const int tid=threadIdx.x, nb=blockIdx.x*128;
    const int tx=tid&7, ty=tid>>3, c0=tx*4;
    for(int i=tid;i<8192;i+=256) s[C_NW1+i]=node_w1[i];
    for(int i=tid;i<4096;i+=256) s[C_NW2+i]=node_w2[i];
    if(tid<64){s[C_NB1+tid]=node_b1[tid];s[C_NB2+tid]=node_b2[tid];}
    for(int i=tid;i<128*16;i+=256){
        int l=i>>4,o4=(i&15)<<2; size_t b=(size_t)(nb+l)*64+o4;
        *(float4*)(s+C_BA+l*STRIDE+o4)=*(const float4*)(g_h1+b);
        *(float4*)(s+C_BB+l*STRIDE+o4)=*(const float4*)(g_agg+b);
    }
    __syncthreads();
    u64 acc[4][4];
#pragma unroll
    for(int i=0;i<4;++i){
        acc[i][0]=pk(s[C_NB1+c0],s[C_NB1+c0+1]);acc[i][1]=pk(s[C_NB1+c0+2],s[C_NB1+c0+3]);
        acc[i][2]=pk(s[C_NB1+c0+32],s[C_NB1+c0+33]);acc[i][3]=pk(s[C_NB1+c0+34],s[C_NB1+c0+35]);
    }
    gemm4<64>(s+C_BA,s+C_NW1,ty,c0,acc);
    gemm4<64>(s+C_BB,s+C_NW1+64*64,ty,c0,acc);
#pragma unroll
    for(int i=0;i<4;++i){
        float* d=s+C_BT+(ty*4+i)*STRIDE; float a,b;
        upk(acc[i][0],a,b);d[c0+0]=silu(a);d[c0+1]=silu(b);
        upk(acc[i][1],a,b);d[c0+2]=silu(a);d[c0+3]=silu(b);
        upk(acc[i][2],a,b);d[c0+32]=silu(a);d[c0+33]=silu(b);
        upk(acc[i][3],a,b);d[c0+34]=silu(a);d[c0+35]=silu(b);
    }
    __syncthreads();
#pragma unroll
    for(int i=0;i<4;++i){
        acc[i][0]=pk(s[C_NB2+c0],s[C_NB2+c0+1]);acc[i][1]=pk(s[C_NB2+c0+2],s[C_NB2+c0+3]);
        acc[i][2]=pk(s[C_NB2+c0+32],s[C_NB2+c0+33]);acc[i][3]=pk(s[C_NB2+c0+34],s[C_NB2+c0+35]);
    }
    gemm4<64>(s+C_BT,s+C_NW2,ty,c0,acc);
#pragma unroll
    for(int i=0;i<4;++i){
        int l=ty*4+i,node=nb+l; float nm=node_mask[node];
        const float* h1p=s+C_BA+l*STRIDE; float a,b,v0,v1,v2,v3;
        size_t base=(size_t)node*64;
        upk(acc[i][0],a,b);v0=(h1p[c0+0]+a)*nm;v1=(h1p[c0+1]+b)*nm;
        upk(acc[i][1],a,b);v2=(h1p[c0+2]+a)*nm;v3=(h1p[c0+3]+b)*nm;
        *(float4*)(outH+base+c0)=make_float4(v0,v1,v2,v3);
        upk(acc[i][2],a,b);v0=(h1p[c0+32]+a)*nm;v1=(h1p[c0+33]+b)*nm;
        upk(acc[i][3],a,b);v2=(h1p[c0+34]+a)*nm;v3=(h1p[c0+35]+b)*nm;
        *(float4*)(outH+base+c0+32)=make_float4(v0,v1,v2,v3);
    }
}

/* =================== launcher =================== */
extern "C" void kernel_launch(void* const* d_in, const int* in_sizes, int n_in,
                              void* d_out, int out_size)
{
    const float* h          =(const float*)d_in[0];
    const float* coord      =(const float*)d_in[1];
    const float* edge_attr  =(const float*)d_in[2];
    const float* jt_mess    =(const float*)d_in[3];
    const float* node_embed =(const float*)d_in[4];
    const float* node_mask  =(const float*)d_in[5];
    const float* edge_mask  =(const float*)d_in[6];
    const float* mes_w1     =(const float*)d_in[7];
    const float* mes_b1     =(const float*)d_in[8];
    const float* mes_w2     =(const float*)d_in[9];
    const float* mes_b2     =(const float*)d_in[10];
    const float* edge_w1    =(const float*)d_in[11];
    const float* edge_b1    =(const float*)d_in[12];
    const float* edge_w2    =(const float*)d_in[13];
    const float* edge_b2    =(const float*)d_in[14];
    const float* node_w1    =(const float*)d_in[15];
    const float* node_b1    =(const float*)d_in[16];
    const float* node_w2    =(const float*)d_in[17];
    const float* node_b2    =(const float*)d_in[18];
    const float* coord_w1   =(const float*)d_in[19];
    const float* coord_b1   =(const float*)d_in[20];
    const float* coord_w2   =(const float*)d_in[21];
    const int*   edge_index =(const int*)d_in[22];
    const int*   mess_holder=(const int*)d_in[23];
    const int*   node_holder=(const int*)d_in[24];
    const int*   jt_idx     =(const int*)d_in[25];

    float* outH=(float*)d_out;
    float* outC=outH+(size_t)NN*64;
    float* outE=outC+(size_t)NN*3;

    const int smemA=A_SMEMF*4, smemB=B_SMEMF*4, smemC=C_SMEMF*4;
    cudaFuncSetAttribute(kernel_prep, cudaFuncAttributeMaxDynamicSharedMemorySize,smemA);
    cudaFuncSetAttribute(kernel_edges,cudaFuncAttributeMaxDynamicSharedMemorySize,smemB);
    cudaFuncSetAttribute(kernel_nodes,cudaFuncAttributeMaxDynamicSharedMemorySize,smemC);

    kernel_prep<<<NN/128,256,smemA>>>(h,node_embed,mes_w1,node_holder,jt_idx);
    kernel_edges<<<148,TBE,smemB>>>(coord,edge_attr,jt_mess,node_mask,edge_mask,
                                    mes_w1,mes_b1,mes_w2,mes_b2,
                                    edge_w1,edge_b1,edge_w2,edge_b2,
                                    coord_w1,coord_b1,coord_w2,
                                    edge_index+NE,mess_holder,jt_idx,outC,outE);
    kernel_nodes<<<NN/128,256,smemC>>>(node_w1,node_b1,node_w2,node_b2,node_mask,outH);
}